// round 2
// baseline (speedup 1.0000x reference)
#include <cuda_runtime.h>
#include <cuda_bf16.h>
#include <cstdint>

// GATLayer via CSR-by-dst gather:
//   h = x@W (tiled GEMM) -> per-node att dots -> CSR build (count/scan/fill)
//   -> fused gather: per-dst softmax-weighted sum + bias + ELU (no atomics on out).
//
// N = 50000, F_IN = 256, HEADS = 8, C = 32, E = 800000 (+N self loops).

#define F_IN   256
#define F_OUT  256
#define HEADS  8
#define MAXN   50048
#define MAXE   860000   // 800000 edges + 50000 self loops + slack

// -------- scratch (__device__ globals; no allocation allowed) --------
__device__ __align__(16) float g_h[(size_t)MAXN * F_OUT];     // ~51.25 MB
__device__ __align__(16) float g_asrc[(size_t)MAXN * HEADS];
__device__ __align__(16) float g_adst[(size_t)MAXN * HEADS];
__device__ int g_deg[MAXN];
__device__ int g_rowstart[MAXN + 1];
__device__ int g_cursor[MAXN];
__device__ int g_csr_src[MAXE];

// ============================================================================
// Kernel 1: GEMM  g_h = x @ W     (64x64 tile, BK=16, 4x4 microtile)
// ============================================================================
#define BM 64
#define BN 64
#define BK 16
__global__ __launch_bounds__(256) void gemm_kernel(
    const float* __restrict__ X, const float* __restrict__ W, int N)
{
    __shared__ float As[BK][BM];
    __shared__ float Bs[BK][BN];

    const int tid = threadIdx.x;
    const int block_row = blockIdx.x * BM;
    const int block_col = blockIdx.y * BN;
    const int ty = tid >> 4;
    const int tx = tid & 15;

    const int arow  = tid >> 2;
    const int acol4 = (tid & 3) << 2;
    const int brow  = tid >> 4;
    const int bcol4 = (tid & 15) << 2;

    const bool arow_ok = (block_row + arow) < N;

    float acc[4][4];
#pragma unroll
    for (int i = 0; i < 4; i++)
#pragma unroll
        for (int j = 0; j < 4; j++) acc[i][j] = 0.f;

    for (int kt = 0; kt < F_IN; kt += BK) {
        float4 a4 = make_float4(0.f, 0.f, 0.f, 0.f);
        if (arow_ok)
            a4 = *(const float4*)&X[(size_t)(block_row + arow) * F_IN + kt + acol4];
        As[acol4 + 0][arow] = a4.x;
        As[acol4 + 1][arow] = a4.y;
        As[acol4 + 2][arow] = a4.z;
        As[acol4 + 3][arow] = a4.w;

        *(float4*)&Bs[brow][bcol4] =
            *(const float4*)&W[(size_t)(kt + brow) * F_OUT + block_col + bcol4];
        __syncthreads();

#pragma unroll
        for (int k = 0; k < BK; k++) {
            float4 av = *(const float4*)&As[k][ty << 2];
            float4 bv = *(const float4*)&Bs[k][tx << 2];
            float a_[4] = {av.x, av.y, av.z, av.w};
            float b_[4] = {bv.x, bv.y, bv.z, bv.w};
#pragma unroll
            for (int i = 0; i < 4; i++)
#pragma unroll
                for (int j = 0; j < 4; j++)
                    acc[i][j] = fmaf(a_[i], b_[j], acc[i][j]);
        }
        __syncthreads();
    }

#pragma unroll
    for (int i = 0; i < 4; i++) {
        int row = block_row + (ty << 2) + i;
        if (row < N) {
            float4 v = make_float4(acc[i][0], acc[i][1], acc[i][2], acc[i][3]);
            *(float4*)&g_h[(size_t)row * F_OUT + block_col + (tx << 2)] = v;
        }
    }
}

// ============================================================================
// Kernel 2: per-node attention dots; also seed deg[n]=1 (self loop).
// ============================================================================
__global__ __launch_bounds__(256) void attdot_kernel(
    const float* __restrict__ att_src, const float* __restrict__ att_dst)
{
    const int n = blockIdx.x;
    const int tid = threadIdx.x;
    const int lane = tid & 31;
    const int w = tid >> 5;

    float hv = g_h[(size_t)n * F_OUT + tid];
    float s = hv * att_src[tid];
    float d = hv * att_dst[tid];
#pragma unroll
    for (int o = 16; o > 0; o >>= 1) {
        s += __shfl_down_sync(0xffffffffu, s, o);
        d += __shfl_down_sync(0xffffffffu, d, o);
    }
    if (lane == 0) {
        g_asrc[n * HEADS + w] = s;
        g_adst[n * HEADS + w] = d;
    }
    if (tid == 0) g_deg[n] = 1;   // self loop pre-counted
}

// ============================================================================
// Kernel 3: degree count over real edges
// ============================================================================
__global__ __launch_bounds__(256) void count_kernel(const int* __restrict__ ei, int E)
{
    int e = blockIdx.x * blockDim.x + threadIdx.x;
    if (e >= E) return;
    atomicAdd(&g_deg[ei[E + e]], 1);
}

// ============================================================================
// Kernel 4: single-block exclusive scan -> row_start, cursor
// ============================================================================
__global__ __launch_bounds__(1024) void scan_kernel(int N)
{
    __shared__ int ssum[1024];
    const int tid = threadIdx.x;
    const int chunk = (N + 1023) / 1024;
    const int beg = tid * chunk;
    const int end = min(beg + chunk, N);

    int s = 0;
    for (int i = beg; i < end; i++) s += g_deg[i];
    ssum[tid] = s;
    __syncthreads();

    // Hillis-Steele inclusive scan
    for (int off = 1; off < 1024; off <<= 1) {
        int v = (tid >= off) ? ssum[tid - off] : 0;
        __syncthreads();
        ssum[tid] += v;
        __syncthreads();
    }

    int run = (tid == 0) ? 0 : ssum[tid - 1];
    for (int i = beg; i < end; i++) {
        int d = g_deg[i];
        g_rowstart[i] = run;
        g_cursor[i]   = run;
        run += d;
    }
    if (end == N && beg < N) g_rowstart[N] = run;
    if (N == 0 && tid == 0) g_rowstart[0] = 0;
}

// ============================================================================
// Kernel 5: CSR fill (edges + self loops)
// ============================================================================
__global__ __launch_bounds__(256) void fill_kernel(const int* __restrict__ ei, int E, int N)
{
    int e = blockIdx.x * blockDim.x + threadIdx.x;
    int total = E + N;
    if (e >= total) return;
    int src, dst;
    if (e < E) { src = ei[e]; dst = ei[E + e]; }
    else       { src = dst = e - E; }
    int pos = atomicAdd(&g_cursor[dst], 1);
    g_csr_src[pos] = src;
}

// ============================================================================
// Kernel 6: fused gather: per-dst softmax-weighted sum + bias + ELU.
//   block = dst node, 256 threads. Warp w owns head w's 32 channels.
// ============================================================================
__global__ __launch_bounds__(256) void gather_kernel(
    float* __restrict__ out, const float* __restrict__ bias)
{
    const int n = blockIdx.x;
    const int tid = threadIdx.x;
    const int lane = tid & 31;
    const int h = tid >> 5;

    const int beg = g_rowstart[n];
    const int end = g_rowstart[n + 1];

    const float adst = g_adst[n * HEADS + h];

    float acc = 0.f;
    float denom = 0.f;

    int i = beg;
    // 2-wide unroll for MLP on the h-row loads
    for (; i + 1 < end; i += 2) {
        int s0 = g_csr_src[i];
        int s1 = g_csr_src[i + 1];
        float w0 = 0.f, w1 = 0.f;
        if (lane == 0) {
            float a0 = g_asrc[s0 * HEADS + h] + adst;
            float a1 = g_asrc[s1 * HEADS + h] + adst;
            a0 = a0 > 0.f ? a0 : 0.2f * a0;
            a1 = a1 > 0.f ? a1 : 0.2f * a1;
            w0 = __expf(a0);
            w1 = __expf(a1);
        }
        w0 = __shfl_sync(0xffffffffu, w0, 0);
        w1 = __shfl_sync(0xffffffffu, w1, 0);
        float h0 = g_h[(size_t)s0 * F_OUT + tid];
        float h1 = g_h[(size_t)s1 * F_OUT + tid];
        acc = fmaf(w0, h0, acc);
        acc = fmaf(w1, h1, acc);
        denom += w0 + w1;
    }
    if (i < end) {
        int s0 = g_csr_src[i];
        float w0 = 0.f;
        if (lane == 0) {
            float a0 = g_asrc[s0 * HEADS + h] + adst;
            a0 = a0 > 0.f ? a0 : 0.2f * a0;
            w0 = __expf(a0);
        }
        w0 = __shfl_sync(0xffffffffu, w0, 0);
        acc = fmaf(w0, g_h[(size_t)s0 * F_OUT + tid], acc);
        denom += w0;
    }

    float v = acc / (denom + 1e-16f) + bias[tid];
    out[(size_t)n * F_OUT + tid] = v > 0.f ? v : expm1f(v);
}

// ============================================================================
extern "C" void kernel_launch(void* const* d_in, const int* in_sizes, int n_in,
                              void* d_out, int out_size)
{
    const float* x       = (const float*)d_in[0];
    const int*   ei      = (const int*)  d_in[1];
    const float* W       = (const float*)d_in[2];
    const float* bias    = (const float*)d_in[5];
    const float* att_src = (const float*)d_in[3];
    const float* att_dst = (const float*)d_in[4];
    float* out = (float*)d_out;

    const int N = in_sizes[0] / F_IN;     // 50000
    const int E = in_sizes[1] / 2;        // 800000
    const int total = E + N;

    dim3 ggrid((N + BM - 1) / BM, F_OUT / BN);
    gemm_kernel<<<ggrid, 256>>>(x, W, N);

    attdot_kernel<<<N, 256>>>(att_src, att_dst);

    count_kernel<<<(E + 255) / 256, 256>>>(ei, E);
    scan_kernel<<<1, 1024>>>(N);
    fill_kernel<<<(total + 255) / 256, 256>>>(ei, E, N);

    gather_kernel<<<N, 256>>>(out, bias);
}

// round 3
// speedup vs baseline: 1.2713x; 1.2713x over previous
#include <cuda_runtime.h>
#include <cuda_bf16.h>
#include <cstdint>

// GATLayer via CSR-by-dst gather, order-free segment allocation:
//   h = x@W -> att dots -> deg count -> block-scan+atomic alloc -> fill
//   (writes csr_src AND per-edge per-head exp weights) -> fused gather
//   (weighted sum + normalize + bias + ELU).
//
// N = 50000, F_IN = 256, HEADS = 8, C = 32, E = 800000 (+N self loops).

#define F_IN   256
#define F_OUT  256
#define HEADS  8
#define MAXN   50048
#define MAXE   860000

// -------- scratch (__device__ globals; no allocation allowed) --------
__device__ __align__(16) float g_h[(size_t)MAXN * F_OUT];       // ~51.25 MB
__device__ __align__(16) float g_asrc[(size_t)MAXN * HEADS];
__device__ __align__(16) float g_adst[(size_t)MAXN * HEADS];
__device__ __align__(32) float g_wcsr[(size_t)MAXE * HEADS];    // ~27.5 MB
__device__ int g_deg[MAXN];
__device__ int g_rowstart[MAXN];
__device__ int g_cursor[MAXN];
__device__ int g_csr_src[MAXE];
__device__ int g_total;

// ============================================================================
// Kernel 1: GEMM  g_h = x @ W     (64x64 tile, BK=16, 4x4 microtile)
// ============================================================================
#define BM 64
#define BN 64
#define BK 16
__global__ __launch_bounds__(256) void gemm_kernel(
    const float* __restrict__ X, const float* __restrict__ W, int N)
{
    __shared__ float As[BK][BM];
    __shared__ float Bs[BK][BN];

    const int tid = threadIdx.x;
    const int block_row = blockIdx.x * BM;
    const int block_col = blockIdx.y * BN;
    const int ty = tid >> 4;
    const int tx = tid & 15;

    const int arow  = tid >> 2;
    const int acol4 = (tid & 3) << 2;
    const int brow  = tid >> 4;
    const int bcol4 = (tid & 15) << 2;

    const bool arow_ok = (block_row + arow) < N;

    float acc[4][4];
#pragma unroll
    for (int i = 0; i < 4; i++)
#pragma unroll
        for (int j = 0; j < 4; j++) acc[i][j] = 0.f;

    for (int kt = 0; kt < F_IN; kt += BK) {
        float4 a4 = make_float4(0.f, 0.f, 0.f, 0.f);
        if (arow_ok)
            a4 = *(const float4*)&X[(size_t)(block_row + arow) * F_IN + kt + acol4];
        As[acol4 + 0][arow] = a4.x;
        As[acol4 + 1][arow] = a4.y;
        As[acol4 + 2][arow] = a4.z;
        As[acol4 + 3][arow] = a4.w;

        *(float4*)&Bs[brow][bcol4] =
            *(const float4*)&W[(size_t)(kt + brow) * F_OUT + block_col + bcol4];
        __syncthreads();

#pragma unroll
        for (int k = 0; k < BK; k++) {
            float4 av = *(const float4*)&As[k][ty << 2];
            float4 bv = *(const float4*)&Bs[k][tx << 2];
            float a_[4] = {av.x, av.y, av.z, av.w};
            float b_[4] = {bv.x, bv.y, bv.z, bv.w};
#pragma unroll
            for (int i = 0; i < 4; i++)
#pragma unroll
                for (int j = 0; j < 4; j++)
                    acc[i][j] = fmaf(a_[i], b_[j], acc[i][j]);
        }
        __syncthreads();
    }

#pragma unroll
    for (int i = 0; i < 4; i++) {
        int row = block_row + (ty << 2) + i;
        if (row < N) {
            float4 v = make_float4(acc[i][0], acc[i][1], acc[i][2], acc[i][3]);
            *(float4*)&g_h[(size_t)row * F_OUT + block_col + (tx << 2)] = v;
        }
    }
}

// ============================================================================
// Kernel 2: per-node attention dots; seed deg[n]=1 (self loop); reset g_total.
// ============================================================================
__global__ __launch_bounds__(256) void attdot_kernel(
    const float* __restrict__ att_src, const float* __restrict__ att_dst)
{
    const int n = blockIdx.x;
    const int tid = threadIdx.x;
    const int lane = tid & 31;
    const int w = tid >> 5;

    float hv = g_h[(size_t)n * F_OUT + tid];
    float s = hv * att_src[tid];
    float d = hv * att_dst[tid];
#pragma unroll
    for (int o = 16; o > 0; o >>= 1) {
        s += __shfl_down_sync(0xffffffffu, s, o);
        d += __shfl_down_sync(0xffffffffu, d, o);
    }
    if (lane == 0) {
        g_asrc[n * HEADS + w] = s;
        g_adst[n * HEADS + w] = d;
    }
    if (tid == 0) {
        g_deg[n] = 1;                 // self loop pre-counted
        if (n == 0) g_total = 0;
    }
}

// ============================================================================
// Kernel 3: degree count over real edges
// ============================================================================
__global__ __launch_bounds__(256) void count_kernel(const int* __restrict__ ei, int E)
{
    int e = blockIdx.x * blockDim.x + threadIdx.x;
    if (e >= E) return;
    atomicAdd(&g_deg[ei[E + e]], 1);
}

// ============================================================================
// Kernel 4: segment allocation (order-free). Block-level scan + 1 atomic/block.
// ============================================================================
__global__ __launch_bounds__(256) void alloc_kernel(int N)
{
    __shared__ int warp_excl[8];
    __shared__ int blk_base;

    const int tid = threadIdx.x;
    const int lane = tid & 31;
    const int w = tid >> 5;
    const int n = blockIdx.x * 256 + tid;

    int deg = (n < N) ? g_deg[n] : 0;

    // warp inclusive scan
    int incl = deg;
#pragma unroll
    for (int off = 1; off < 32; off <<= 1) {
        int v = __shfl_up_sync(0xffffffffu, incl, off);
        if (lane >= off) incl += v;
    }
    if (lane == 31) warp_excl[w] = incl;   // warp totals, scanned below
    __syncthreads();
    if (tid == 0) {
        int run = 0;
#pragma unroll
        for (int i = 0; i < 8; i++) { int t = warp_excl[i]; warp_excl[i] = run; run += t; }
        blk_base = atomicAdd(&g_total, run);
    }
    __syncthreads();

    if (n < N) {
        int start = blk_base + warp_excl[w] + incl - deg;
        g_rowstart[n] = start;
        g_cursor[n]   = start;
    }
}

// ============================================================================
// Kernel 5: CSR fill (edges + self loops) + per-edge per-head exp weights
// ============================================================================
__global__ __launch_bounds__(256) void fill_kernel(const int* __restrict__ ei, int E, int N)
{
    int e = blockIdx.x * blockDim.x + threadIdx.x;
    int total = E + N;
    if (e >= total) return;
    int src, dst;
    if (e < E) { src = ei[e]; dst = ei[E + e]; }
    else       { src = dst = e - E; }

    int pos = atomicAdd(&g_cursor[dst], 1);
    g_csr_src[pos] = src;

    float4 s0 = *(const float4*)&g_asrc[src * HEADS];
    float4 s1 = *(const float4*)&g_asrc[src * HEADS + 4];
    float4 d0 = *(const float4*)&g_adst[dst * HEADS];
    float4 d1 = *(const float4*)&g_adst[dst * HEADS + 4];

    float a[8] = {s0.x + d0.x, s0.y + d0.y, s0.z + d0.z, s0.w + d0.w,
                  s1.x + d1.x, s1.y + d1.y, s1.z + d1.z, s1.w + d1.w};
#pragma unroll
    for (int h = 0; h < 8; h++) {
        float v = a[h];
        v = v > 0.f ? v : 0.2f * v;
        a[h] = __expf(v);
    }
    float* wp = &g_wcsr[(size_t)pos * HEADS];
    *(float4*)wp       = make_float4(a[0], a[1], a[2], a[3]);
    *(float4*)(wp + 4) = make_float4(a[4], a[5], a[6], a[7]);
}

// ============================================================================
// Kernel 6: fused gather: per-dst weighted sum + normalize + bias + ELU.
//   block = dst node, 256 threads; warp w handles head w's 32 channels.
// ============================================================================
__global__ __launch_bounds__(256) void gather_kernel(
    float* __restrict__ out, const float* __restrict__ bias)
{
    const int n = blockIdx.x;
    const int tid = threadIdx.x;
    const int h = tid >> 5;

    const int beg = g_rowstart[n];
    const int end = beg + g_deg[n];

    float acc = 0.f;
    float denom = 0.f;

    int i = beg;
    for (; i + 3 < end; i += 4) {
        int s0 = __ldg(&g_csr_src[i]);
        int s1 = __ldg(&g_csr_src[i + 1]);
        int s2 = __ldg(&g_csr_src[i + 2]);
        int s3 = __ldg(&g_csr_src[i + 3]);
        float w0 = __ldg(&g_wcsr[(size_t)(i    ) * HEADS + h]);
        float w1 = __ldg(&g_wcsr[(size_t)(i + 1) * HEADS + h]);
        float w2 = __ldg(&g_wcsr[(size_t)(i + 2) * HEADS + h]);
        float w3 = __ldg(&g_wcsr[(size_t)(i + 3) * HEADS + h]);
        float h0 = g_h[(size_t)s0 * F_OUT + tid];
        float h1 = g_h[(size_t)s1 * F_OUT + tid];
        float h2 = g_h[(size_t)s2 * F_OUT + tid];
        float h3 = g_h[(size_t)s3 * F_OUT + tid];
        acc = fmaf(w0, h0, acc);
        acc = fmaf(w1, h1, acc);
        acc = fmaf(w2, h2, acc);
        acc = fmaf(w3, h3, acc);
        denom += (w0 + w1) + (w2 + w3);
    }
    for (; i < end; i++) {
        int s0 = __ldg(&g_csr_src[i]);
        float w0 = __ldg(&g_wcsr[(size_t)i * HEADS + h]);
        acc = fmaf(w0, g_h[(size_t)s0 * F_OUT + tid], acc);
        denom += w0;
    }

    float v = acc / (denom + 1e-16f) + bias[tid];
    out[(size_t)n * F_OUT + tid] = v > 0.f ? v : expm1f(v);
}

// ============================================================================
extern "C" void kernel_launch(void* const* d_in, const int* in_sizes, int n_in,
                              void* d_out, int out_size)
{
    const float* x       = (const float*)d_in[0];
    const int*   ei      = (const int*)  d_in[1];
    const float* W       = (const float*)d_in[2];
    const float* att_src = (const float*)d_in[3];
    const float* att_dst = (const float*)d_in[4];
    const float* bias    = (const float*)d_in[5];
    float* out = (float*)d_out;

    const int N = in_sizes[0] / F_IN;     // 50000
    const int E = in_sizes[1] / 2;        // 800000
    const int total = E + N;

    dim3 ggrid((N + BM - 1) / BM, F_OUT / BN);
    gemm_kernel<<<ggrid, 256>>>(x, W, N);

    attdot_kernel<<<N, 256>>>(att_src, att_dst);

    count_kernel<<<(E + 255) / 256, 256>>>(ei, E);
    alloc_kernel<<<(N + 255) / 256, 256>>>(N);
    fill_kernel<<<(total + 255) / 256, 256>>>(ei, E, N);

    gather_kernel<<<N, 256>>>(out, bias);
}

// round 4
// speedup vs baseline: 1.5010x; 1.1807x over previous
#include <cuda_runtime.h>
#include <cuda_bf16.h>
#include <cstdint>

// GATLayer via CSR-by-dst gather + tf32 tensor-core GEMM:
//   h = x@W (mma.sync tf32) -> att dots -> deg count -> block-scan alloc ->
//   fill (csr_src + per-edge per-head exp weights) -> fused gather
//   (weighted sum + normalize + bias + ELU).
//
// N = 50000, F_IN = 256, HEADS = 8, C = 32, E = 800000 (+N self loops).

#define F_IN   256
#define F_OUT  256
#define HEADS  8
#define MAXN   50048
#define MAXE   860000

// -------- scratch (__device__ globals; no allocation allowed) --------
__device__ __align__(16) float g_h[(size_t)MAXN * F_OUT];       // ~51.25 MB
__device__ __align__(16) float g_asrc[(size_t)MAXN * HEADS];
__device__ __align__(16) float g_adst[(size_t)MAXN * HEADS];
__device__ __align__(32) float g_wcsr[(size_t)MAXE * HEADS];    // ~27.5 MB
__device__ int g_deg[MAXN];
__device__ int g_rowstart[MAXN];
__device__ int g_cursor[MAXN];
__device__ int g_csr_src[MAXE];
__device__ int g_total;

// ============================================================================
// Kernel 1: tf32 tensor-core GEMM  g_h = x @ W
//   128x128 block tile, BK=32, 8 warps (2x4), warp tile 64x32, m16n8k8.
// ============================================================================
#define GBM 128
#define GBN 128
#define GBK 32
#define ASTR 33     // A smem row stride (floats)
#define BSTR 129    // B smem row stride (floats)

__device__ __forceinline__ uint32_t f2tf32(float v) {
    uint32_t u;
    asm("cvt.rna.tf32.f32 %0, %1;" : "=r"(u) : "f"(v));
    return u;
}

__global__ __launch_bounds__(256, 2) void gemm_tf32_kernel(
    const float* __restrict__ X, const float* __restrict__ W, int N)
{
    __shared__ float As[GBM * ASTR];   // [row][k] stride 33
    __shared__ float Bs[GBK * BSTR];   // [k][col] stride 129

    const int tid  = threadIdx.x;
    const int lane = tid & 31;
    const int warp = tid >> 5;
    const int wm = warp & 1;           // 0..1 -> M offset wm*64
    const int wn = warp >> 1;          // 0..3 -> N offset wn*32
    const int tg = lane & 3;           // thread-in-group
    const int gp = lane >> 2;          // group id (0..7)

    const int brow = blockIdx.x * GBM;
    const int bcol = blockIdx.y * GBN;

    // global load mappings
    const int a_r = tid >> 3;          // 0..31 (row step 32)
    const int a_c = (tid & 7) << 2;    // 0,4,...,28
    const int b_k = tid >> 6;          // 0..3 (k step 4 -> 8 iters? no: 32/4=8)
    const int b_c = (tid & 63) << 1;   // 0..126 step 2  -> float2 per thread? keep float4 variant below

    float acc[4][4][4];                // [mt][nt][reg]
#pragma unroll
    for (int mt = 0; mt < 4; mt++)
#pragma unroll
        for (int nt = 0; nt < 4; nt++)
#pragma unroll
            for (int r = 0; r < 4; r++) acc[mt][nt][r] = 0.f;

    for (int kt = 0; kt < F_IN; kt += GBK) {
        // ---- load A tile: 128x32, 4 rounds of (row = a_r + 32*i) ----
#pragma unroll
        for (int i = 0; i < 4; i++) {
            int row = a_r + (i << 5);
            int grow = brow + row;
            float4 v = make_float4(0.f, 0.f, 0.f, 0.f);
            if (grow < N)
                v = *(const float4*)&X[(size_t)grow * F_IN + kt + a_c];
            float* dst = &As[row * ASTR + a_c];
            dst[0] = __uint_as_float(f2tf32(v.x));
            dst[1] = __uint_as_float(f2tf32(v.y));
            dst[2] = __uint_as_float(f2tf32(v.z));
            dst[3] = __uint_as_float(f2tf32(v.w));
        }
        // ---- load B tile: 32x128, thread -> float4, k = tid/32 + 8*i ----
#pragma unroll
        for (int i = 0; i < 4; i++) {
            int k = (tid >> 5) + (i << 3);
            int c4 = (tid & 31) << 2;
            float4 v = *(const float4*)&W[(size_t)(kt + k) * F_OUT + bcol + c4];
            float* dst = &Bs[k * BSTR + c4];
            dst[0] = __uint_as_float(f2tf32(v.x));
            dst[1] = __uint_as_float(f2tf32(v.y));
            dst[2] = __uint_as_float(f2tf32(v.z));
            dst[3] = __uint_as_float(f2tf32(v.w));
        }
        __syncthreads();

#pragma unroll
        for (int ks = 0; ks < 4; ks++) {
            const int k8 = ks << 3;
            uint32_t afr[4][4];
#pragma unroll
            for (int mt = 0; mt < 4; mt++) {
                int r0 = wm * 64 + mt * 16 + gp;
                const float* ap = &As[r0 * ASTR + k8 + tg];
                afr[mt][0] = __float_as_uint(ap[0]);
                afr[mt][1] = __float_as_uint(ap[8 * ASTR]);
                afr[mt][2] = __float_as_uint(ap[4]);
                afr[mt][3] = __float_as_uint(ap[8 * ASTR + 4]);
            }
            uint32_t bfr[4][2];
#pragma unroll
            for (int nt = 0; nt < 4; nt++) {
                int c0 = wn * 32 + nt * 8 + gp;
                const float* bp = &Bs[(k8 + tg) * BSTR + c0];
                bfr[nt][0] = __float_as_uint(bp[0]);
                bfr[nt][1] = __float_as_uint(bp[4 * BSTR]);
            }
#pragma unroll
            for (int mt = 0; mt < 4; mt++)
#pragma unroll
                for (int nt = 0; nt < 4; nt++) {
                    asm volatile(
                        "mma.sync.aligned.m16n8k8.row.col.f32.tf32.tf32.f32 "
                        "{%0,%1,%2,%3}, {%4,%5,%6,%7}, {%8,%9}, {%0,%1,%2,%3};"
                        : "+f"(acc[mt][nt][0]), "+f"(acc[mt][nt][1]),
                          "+f"(acc[mt][nt][2]), "+f"(acc[mt][nt][3])
                        : "r"(afr[mt][0]), "r"(afr[mt][1]),
                          "r"(afr[mt][2]), "r"(afr[mt][3]),
                          "r"(bfr[nt][0]), "r"(bfr[nt][1]));
                }
        }
        __syncthreads();
    }

    // ---- epilogue: write C ----
#pragma unroll
    for (int mt = 0; mt < 4; mt++) {
        int r0 = brow + wm * 64 + mt * 16 + gp;
        int r1 = r0 + 8;
#pragma unroll
        for (int nt = 0; nt < 4; nt++) {
            int c = bcol + wn * 32 + nt * 8 + tg * 2;
            if (r0 < N)
                *(float2*)&g_h[(size_t)r0 * F_OUT + c] =
                    make_float2(acc[mt][nt][0], acc[mt][nt][1]);
            if (r1 < N)
                *(float2*)&g_h[(size_t)r1 * F_OUT + c] =
                    make_float2(acc[mt][nt][2], acc[mt][nt][3]);
        }
    }
}

// ============================================================================
// Kernel 2: per-node attention dots; seed deg[n]=1 (self loop); reset g_total.
// ============================================================================
__global__ __launch_bounds__(256) void attdot_kernel(
    const float* __restrict__ att_src, const float* __restrict__ att_dst)
{
    const int n = blockIdx.x;
    const int tid = threadIdx.x;
    const int lane = tid & 31;
    const int w = tid >> 5;

    float hv = g_h[(size_t)n * F_OUT + tid];
    float s = hv * att_src[tid];
    float d = hv * att_dst[tid];
#pragma unroll
    for (int o = 16; o > 0; o >>= 1) {
        s += __shfl_down_sync(0xffffffffu, s, o);
        d += __shfl_down_sync(0xffffffffu, d, o);
    }
    if (lane == 0) {
        g_asrc[n * HEADS + w] = s;
        g_adst[n * HEADS + w] = d;
    }
    if (tid == 0) {
        g_deg[n] = 1;                 // self loop pre-counted
        if (n == 0) g_total = 0;
    }
}

// ============================================================================
// Kernel 3: degree count over real edges
// ============================================================================
__global__ __launch_bounds__(256) void count_kernel(const int* __restrict__ ei, int E)
{
    int e = blockIdx.x * blockDim.x + threadIdx.x;
    if (e >= E) return;
    atomicAdd(&g_deg[ei[E + e]], 1);
}

// ============================================================================
// Kernel 4: segment allocation (order-free). Block-level scan + 1 atomic/block.
// ============================================================================
__global__ __launch_bounds__(256) void alloc_kernel(int N)
{
    __shared__ int warp_excl[8];
    __shared__ int blk_base;

    const int tid = threadIdx.x;
    const int lane = tid & 31;
    const int w = tid >> 5;
    const int n = blockIdx.x * 256 + tid;

    int deg = (n < N) ? g_deg[n] : 0;

    int incl = deg;
#pragma unroll
    for (int off = 1; off < 32; off <<= 1) {
        int v = __shfl_up_sync(0xffffffffu, incl, off);
        if (lane >= off) incl += v;
    }
    if (lane == 31) warp_excl[w] = incl;
    __syncthreads();
    if (tid == 0) {
        int run = 0;
#pragma unroll
        for (int i = 0; i < 8; i++) { int t = warp_excl[i]; warp_excl[i] = run; run += t; }
        blk_base = atomicAdd(&g_total, run);
    }
    __syncthreads();

    if (n < N) {
        int start = blk_base + warp_excl[w] + incl - deg;
        g_rowstart[n] = start;
        g_cursor[n]   = start;
    }
}

// ============================================================================
// Kernel 5: CSR fill (edges + self loops) + per-edge per-head exp weights
// ============================================================================
__global__ __launch_bounds__(256) void fill_kernel(const int* __restrict__ ei, int E, int N)
{
    int e = blockIdx.x * blockDim.x + threadIdx.x;
    int total = E + N;
    if (e >= total) return;
    int src, dst;
    if (e < E) { src = ei[e]; dst = ei[E + e]; }
    else       { src = dst = e - E; }

    int pos = atomicAdd(&g_cursor[dst], 1);
    g_csr_src[pos] = src;

    float4 s0 = *(const float4*)&g_asrc[src * HEADS];
    float4 s1 = *(const float4*)&g_asrc[src * HEADS + 4];
    float4 d0 = *(const float4*)&g_adst[dst * HEADS];
    float4 d1 = *(const float4*)&g_adst[dst * HEADS + 4];

    float a[8] = {s0.x + d0.x, s0.y + d0.y, s0.z + d0.z, s0.w + d0.w,
                  s1.x + d1.x, s1.y + d1.y, s1.z + d1.z, s1.w + d1.w};
#pragma unroll
    for (int h = 0; h < 8; h++) {
        float v = a[h];
        v = v > 0.f ? v : 0.2f * v;
        a[h] = __expf(v);
    }
    float* wp = &g_wcsr[(size_t)pos * HEADS];
    *(float4*)wp       = make_float4(a[0], a[1], a[2], a[3]);
    *(float4*)(wp + 4) = make_float4(a[4], a[5], a[6], a[7]);
}

// ============================================================================
// Kernel 6: fused gather: per-dst weighted sum + normalize + bias + ELU.
//   block = dst node, 256 threads; warp w handles head w's 32 channels.
// ============================================================================
__global__ __launch_bounds__(256) void gather_kernel(
    float* __restrict__ out, const float* __restrict__ bias)
{
    const int n = blockIdx.x;
    const int tid = threadIdx.x;
    const int h = tid >> 5;

    const int beg = g_rowstart[n];
    const int end = beg + g_deg[n];

    float acc = 0.f;
    float denom = 0.f;

    int i = beg;
    for (; i + 3 < end; i += 4) {
        int s0 = __ldg(&g_csr_src[i]);
        int s1 = __ldg(&g_csr_src[i + 1]);
        int s2 = __ldg(&g_csr_src[i + 2]);
        int s3 = __ldg(&g_csr_src[i + 3]);
        float w0 = __ldg(&g_wcsr[(size_t)(i    ) * HEADS + h]);
        float w1 = __ldg(&g_wcsr[(size_t)(i + 1) * HEADS + h]);
        float w2 = __ldg(&g_wcsr[(size_t)(i + 2) * HEADS + h]);
        float w3 = __ldg(&g_wcsr[(size_t)(i + 3) * HEADS + h]);
        float h0 = g_h[(size_t)s0 * F_OUT + tid];
        float h1 = g_h[(size_t)s1 * F_OUT + tid];
        float h2 = g_h[(size_t)s2 * F_OUT + tid];
        float h3 = g_h[(size_t)s3 * F_OUT + tid];
        acc = fmaf(w0, h0, acc);
        acc = fmaf(w1, h1, acc);
        acc = fmaf(w2, h2, acc);
        acc = fmaf(w3, h3, acc);
        denom += (w0 + w1) + (w2 + w3);
    }
    for (; i < end; i++) {
        int s0 = __ldg(&g_csr_src[i]);
        float w0 = __ldg(&g_wcsr[(size_t)i * HEADS + h]);
        acc = fmaf(w0, g_h[(size_t)s0 * F_OUT + tid], acc);
        denom += w0;
    }

    float v = acc / (denom + 1e-16f) + bias[tid];
    out[(size_t)n * F_OUT + tid] = v > 0.f ? v : expm1f(v);
}

// ============================================================================
extern "C" void kernel_launch(void* const* d_in, const int* in_sizes, int n_in,
                              void* d_out, int out_size)
{
    const float* x       = (const float*)d_in[0];
    const int*   ei      = (const int*)  d_in[1];
    const float* W       = (const float*)d_in[2];
    const float* att_src = (const float*)d_in[3];
    const float* att_dst = (const float*)d_in[4];
    const float* bias    = (const float*)d_in[5];
    float* out = (float*)d_out;

    const int N = in_sizes[0] / F_IN;     // 50000
    const int E = in_sizes[1] / 2;        // 800000
    const int total = E + N;

    dim3 ggrid((N + GBM - 1) / GBM, F_OUT / GBN);
    gemm_tf32_kernel<<<ggrid, 256>>>(x, W, N);

    attdot_kernel<<<N, 256>>>(att_src, att_dst);

    count_kernel<<<(E + 255) / 256, 256>>>(ei, E);
    alloc_kernel<<<(N + 255) / 256, 256>>>(N);
    fill_kernel<<<(total + 255) / 256, 256>>>(ei, E, N);

    gather_kernel<<<N, 256>>>(out, bias);
}

// round 5
// speedup vs baseline: 1.8028x; 1.2010x over previous
#include <cuda_runtime.h>
#include <cuda_bf16.h>
#include <cstdint>

// GATLayer via CSR-by-dst gather + cp.async double-buffered tf32 GEMM:
//   h = x@W (mma.sync tf32, 2-stage cp.async pipeline) -> att dots ->
//   deg count -> block-scan alloc -> fill (csr_src + per-edge exp weights)
//   -> fused gather (weighted sum + normalize + bias + ELU).
//
// N = 50000, F_IN = 256, HEADS = 8, C = 32, E = 800000 (+N self loops).

#define F_IN   256
#define F_OUT  256
#define HEADS  8
#define MAXN   50048
#define MAXE   860000

// -------- scratch (__device__ globals; no allocation allowed) --------
__device__ __align__(16) float g_h[(size_t)MAXN * F_OUT];       // ~51.25 MB
__device__ __align__(16) float g_asrc[(size_t)MAXN * HEADS];
__device__ __align__(16) float g_adst[(size_t)MAXN * HEADS];
__device__ __align__(32) float g_wcsr[(size_t)MAXE * HEADS];    // ~27.5 MB
__device__ int g_deg[MAXN];
__device__ int g_rowstart[MAXN];
__device__ int g_cursor[MAXN];
__device__ int g_csr_src[MAXE];
__device__ int g_total;

// ============================================================================
// Kernel 1: tf32 tensor-core GEMM  g_h = x @ W
//   128x128 block tile, BK=16, 2-stage cp.async double buffer.
//   8 warps (2x4), warp tile 64x32, m16n8k8. Bank-conflict-free strides.
// ============================================================================
#define GBM 128
#define GBN 128
#define GBK 16
#define ASTR 20     // A smem row stride: gp*20 mod 32 spans multiples of 4
#define BSTR 136    // B smem row stride: 136 mod 32 == 8 -> tg*8+gp distinct
#define KTILES (F_IN / GBK)   // 16

__device__ __forceinline__ uint32_t f2tf32(float v) {
    uint32_t u;
    asm("cvt.rna.tf32.f32 %0, %1;" : "=r"(u) : "f"(v));
    return u;
}

__device__ __forceinline__ void cp16(uint32_t smem_addr, const void* gptr, int pred_bytes) {
    asm volatile("cp.async.cg.shared.global [%0], [%1], 16, %2;"
                 :: "r"(smem_addr), "l"(gptr), "r"(pred_bytes));
}

__global__ __launch_bounds__(256, 2) void gemm_tf32_kernel(
    const float* __restrict__ X, const float* __restrict__ W, int N)
{
    __shared__ float As[2][GBM * ASTR];   // raw f32; cvt at fragment load
    __shared__ float Bs[2][GBK * BSTR];

    const int tid  = threadIdx.x;
    const int lane = tid & 31;
    const int warp = tid >> 5;
    const int wm = warp & 1;
    const int wn = warp >> 1;
    const int tg = lane & 3;
    const int gp = lane >> 2;

    const int brow = blockIdx.x * GBM;
    const int bcol = blockIdx.y * GBN;

    // cp.async mappings (2 float4 each for A and B per thread per stage)
    // A: idx = tid + 256*i -> row = idx>>2 (=tid>>2 + 64i), quad = idx&3
    const int a_row0 = tid >> 2;
    const int a_quad = (tid & 3) << 2;          // float offset 0,4,8,12
    // B: idx = tid + 256*i -> k = idx>>5 (=tid>>5 + 8i), col4 = (idx&31)<<2
    const int b_k0  = tid >> 5;
    const int b_c4  = (lane) << 2;

    uint32_t as_base = (uint32_t)__cvta_generic_to_shared(&As[0][0]);
    uint32_t bs_base = (uint32_t)__cvta_generic_to_shared(&Bs[0][0]);

    float acc[4][4][4];
#pragma unroll
    for (int mt = 0; mt < 4; mt++)
#pragma unroll
        for (int nt = 0; nt < 4; nt++)
#pragma unroll
            for (int r = 0; r < 4; r++) acc[mt][nt][r] = 0.f;

    // ---- prefetch helper (stage s, k-tile kt) ----
    auto prefetch = [&](int s, int kt) {
#pragma unroll
        for (int i = 0; i < 2; i++) {
            int row = a_row0 + (i << 6);
            int grow = brow + row;
            int ok = (grow < N) ? 16 : 0;
            uint32_t dst = as_base + (uint32_t)((s * GBM * ASTR + row * ASTR + a_quad) << 2);
            cp16(dst, &X[(size_t)grow * F_IN + kt + a_quad], ok);
        }
#pragma unroll
        for (int i = 0; i < 2; i++) {
            int k = b_k0 + (i << 3);
            uint32_t dst = bs_base + (uint32_t)((s * GBK * BSTR + k * BSTR + b_c4) << 2);
            cp16(dst, &W[(size_t)(kt + k) * F_OUT + bcol + b_c4], 16);
        }
        asm volatile("cp.async.commit_group;");
    };

    prefetch(0, 0);

    for (int t = 0; t < KTILES; t++) {
        const int s = t & 1;
        if (t + 1 < KTILES) {
            prefetch(s ^ 1, (t + 1) * GBK);
            asm volatile("cp.async.wait_group 1;");
        } else {
            asm volatile("cp.async.wait_group 0;");
        }
        __syncthreads();

#pragma unroll
        for (int ks = 0; ks < 2; ks++) {
            const int k8 = ks << 3;
            uint32_t afr[4][4];
#pragma unroll
            for (int mt = 0; mt < 4; mt++) {
                int r0 = wm * 64 + mt * 16 + gp;
                const float* ap = &As[s][r0 * ASTR + k8 + tg];
                afr[mt][0] = f2tf32(ap[0]);
                afr[mt][1] = f2tf32(ap[8 * ASTR]);
                afr[mt][2] = f2tf32(ap[4]);
                afr[mt][3] = f2tf32(ap[8 * ASTR + 4]);
            }
            uint32_t bfr[4][2];
#pragma unroll
            for (int nt = 0; nt < 4; nt++) {
                int c0 = wn * 32 + nt * 8 + gp;
                const float* bp = &Bs[s][(k8 + tg) * BSTR + c0];
                bfr[nt][0] = f2tf32(bp[0]);
                bfr[nt][1] = f2tf32(bp[4 * BSTR]);
            }
#pragma unroll
            for (int mt = 0; mt < 4; mt++)
#pragma unroll
                for (int nt = 0; nt < 4; nt++) {
                    asm volatile(
                        "mma.sync.aligned.m16n8k8.row.col.f32.tf32.tf32.f32 "
                        "{%0,%1,%2,%3}, {%4,%5,%6,%7}, {%8,%9}, {%0,%1,%2,%3};"
                        : "+f"(acc[mt][nt][0]), "+f"(acc[mt][nt][1]),
                          "+f"(acc[mt][nt][2]), "+f"(acc[mt][nt][3])
                        : "r"(afr[mt][0]), "r"(afr[mt][1]),
                          "r"(afr[mt][2]), "r"(afr[mt][3]),
                          "r"(bfr[nt][0]), "r"(bfr[nt][1]));
                }
        }
        __syncthreads();
    }

    // ---- epilogue ----
#pragma unroll
    for (int mt = 0; mt < 4; mt++) {
        int r0 = brow + wm * 64 + mt * 16 + gp;
        int r1 = r0 + 8;
#pragma unroll
        for (int nt = 0; nt < 4; nt++) {
            int c = bcol + wn * 32 + nt * 8 + tg * 2;
            if (r0 < N)
                *(float2*)&g_h[(size_t)r0 * F_OUT + c] =
                    make_float2(acc[mt][nt][0], acc[mt][nt][1]);
            if (r1 < N)
                *(float2*)&g_h[(size_t)r1 * F_OUT + c] =
                    make_float2(acc[mt][nt][2], acc[mt][nt][3]);
        }
    }
}

// ============================================================================
// Kernel 2: per-node attention dots; seed deg[n]=1 (self loop); reset g_total.
// ============================================================================
__global__ __launch_bounds__(256) void attdot_kernel(
    const float* __restrict__ att_src, const float* __restrict__ att_dst)
{
    const int n = blockIdx.x;
    const int tid = threadIdx.x;
    const int lane = tid & 31;
    const int w = tid >> 5;

    float hv = g_h[(size_t)n * F_OUT + tid];
    float s = hv * att_src[tid];
    float d = hv * att_dst[tid];
#pragma unroll
    for (int o = 16; o > 0; o >>= 1) {
        s += __shfl_down_sync(0xffffffffu, s, o);
        d += __shfl_down_sync(0xffffffffu, d, o);
    }
    if (lane == 0) {
        g_asrc[n * HEADS + w] = s;
        g_adst[n * HEADS + w] = d;
    }
    if (tid == 0) {
        g_deg[n] = 1;                 // self loop pre-counted
        if (n == 0) g_total = 0;
    }
}

// ============================================================================
// Kernel 3: degree count over real edges
// ============================================================================
__global__ __launch_bounds__(256) void count_kernel(const int* __restrict__ ei, int E)
{
    int e = blockIdx.x * blockDim.x + threadIdx.x;
    if (e >= E) return;
    atomicAdd(&g_deg[ei[E + e]], 1);
}

// ============================================================================
// Kernel 4: segment allocation (order-free). Block-level scan + 1 atomic/block.
// ============================================================================
__global__ __launch_bounds__(256) void alloc_kernel(int N)
{
    __shared__ int warp_excl[8];
    __shared__ int blk_base;

    const int tid = threadIdx.x;
    const int lane = tid & 31;
    const int w = tid >> 5;
    const int n = blockIdx.x * 256 + tid;

    int deg = (n < N) ? g_deg[n] : 0;

    int incl = deg;
#pragma unroll
    for (int off = 1; off < 32; off <<= 1) {
        int v = __shfl_up_sync(0xffffffffu, incl, off);
        if (lane >= off) incl += v;
    }
    if (lane == 31) warp_excl[w] = incl;
    __syncthreads();
    if (tid == 0) {
        int run = 0;
#pragma unroll
        for (int i = 0; i < 8; i++) { int t = warp_excl[i]; warp_excl[i] = run; run += t; }
        blk_base = atomicAdd(&g_total, run);
    }
    __syncthreads();

    if (n < N) {
        int start = blk_base + warp_excl[w] + incl - deg;
        g_rowstart[n] = start;
        g_cursor[n]   = start;
    }
}

// ============================================================================
// Kernel 5: CSR fill (edges + self loops) + per-edge per-head exp weights
// ============================================================================
__global__ __launch_bounds__(256) void fill_kernel(const int* __restrict__ ei, int E, int N)
{
    int e = blockIdx.x * blockDim.x + threadIdx.x;
    int total = E + N;
    if (e >= total) return;
    int src, dst;
    if (e < E) { src = ei[e]; dst = ei[E + e]; }
    else       { src = dst = e - E; }

    int pos = atomicAdd(&g_cursor[dst], 1);
    g_csr_src[pos] = src;

    float4 s0 = *(const float4*)&g_asrc[src * HEADS];
    float4 s1 = *(const float4*)&g_asrc[src * HEADS + 4];
    float4 d0 = *(const float4*)&g_adst[dst * HEADS];
    float4 d1 = *(const float4*)&g_adst[dst * HEADS + 4];

    float a[8] = {s0.x + d0.x, s0.y + d0.y, s0.z + d0.z, s0.w + d0.w,
                  s1.x + d1.x, s1.y + d1.y, s1.z + d1.z, s1.w + d1.w};
#pragma unroll
    for (int h = 0; h < 8; h++) {
        float v = a[h];
        v = v > 0.f ? v : 0.2f * v;
        a[h] = __expf(v);
    }
    float* wp = &g_wcsr[(size_t)pos * HEADS];
    *(float4*)wp       = make_float4(a[0], a[1], a[2], a[3]);
    *(float4*)(wp + 4) = make_float4(a[4], a[5], a[6], a[7]);
}

// ============================================================================
// Kernel 6: fused gather: per-dst weighted sum + normalize + bias + ELU.
//   block = dst node, 256 threads; warp w handles head w's 32 channels.
// ============================================================================
__global__ __launch_bounds__(256) void gather_kernel(
    float* __restrict__ out, const float* __restrict__ bias)
{
    const int n = blockIdx.x;
    const int tid = threadIdx.x;
    const int h = tid >> 5;

    const int beg = g_rowstart[n];
    const int end = beg + g_deg[n];

    float acc = 0.f;
    float denom = 0.f;

    int i = beg;
    for (; i + 3 < end; i += 4) {
        int s0 = __ldg(&g_csr_src[i]);
        int s1 = __ldg(&g_csr_src[i + 1]);
        int s2 = __ldg(&g_csr_src[i + 2]);
        int s3 = __ldg(&g_csr_src[i + 3]);
        float w0 = __ldg(&g_wcsr[(size_t)(i    ) * HEADS + h]);
        float w1 = __ldg(&g_wcsr[(size_t)(i + 1) * HEADS + h]);
        float w2 = __ldg(&g_wcsr[(size_t)(i + 2) * HEADS + h]);
        float w3 = __ldg(&g_wcsr[(size_t)(i + 3) * HEADS + h]);
        float h0 = g_h[(size_t)s0 * F_OUT + tid];
        float h1 = g_h[(size_t)s1 * F_OUT + tid];
        float h2 = g_h[(size_t)s2 * F_OUT + tid];
        float h3 = g_h[(size_t)s3 * F_OUT + tid];
        acc = fmaf(w0, h0, acc);
        acc = fmaf(w1, h1, acc);
        acc = fmaf(w2, h2, acc);
        acc = fmaf(w3, h3, acc);
        denom += (w0 + w1) + (w2 + w3);
    }
    for (; i < end; i++) {
        int s0 = __ldg(&g_csr_src[i]);
        float w0 = __ldg(&g_wcsr[(size_t)i * HEADS + h]);
        acc = fmaf(w0, g_h[(size_t)s0 * F_OUT + tid], acc);
        denom += w0;
    }

    float v = acc / (denom + 1e-16f) + bias[tid];
    out[(size_t)n * F_OUT + tid] = v > 0.f ? v : expm1f(v);
}

// ============================================================================
extern "C" void kernel_launch(void* const* d_in, const int* in_sizes, int n_in,
                              void* d_out, int out_size)
{
    const float* x       = (const float*)d_in[0];
    const int*   ei      = (const int*)  d_in[1];
    const float* W       = (const float*)d_in[2];
    const float* att_src = (const float*)d_in[3];
    const float* att_dst = (const float*)d_in[4];
    const float* bias    = (const float*)d_in[5];
    float* out = (float*)d_out;

    const int N = in_sizes[0] / F_IN;     // 50000
    const int E = in_sizes[1] / 2;        // 800000
    const int total = E + N;

    dim3 ggrid((N + GBM - 1) / GBM, F_OUT / GBN);
    gemm_tf32_kernel<<<ggrid, 256>>>(x, W, N);

    attdot_kernel<<<N, 256>>>(att_src, att_dst);

    count_kernel<<<(E + 255) / 256, 256>>>(ei, E);
    alloc_kernel<<<(N + 255) / 256, 256>>>(N);
    fill_kernel<<<(total + 255) / 256, 256>>>(ei, E, N);

    gather_kernel<<<N, 256>>>(out, bias);
}

// round 6
// speedup vs baseline: 2.4323x; 1.3492x over previous
#include <cuda_runtime.h>
#include <cuda_fp16.h>
#include <cuda_bf16.h>
#include <cstdint>

// GATLayer: tf32 cp.async GEMM -> fp16 h -> att dots -> CSR build ->
// fused gather (inline lane-distributed exp weights, fp32 accum) + bias + ELU.
//
// N = 50000, F_IN = 256, HEADS = 8, C = 32, E = 800000 (+N self loops).

#define F_IN   256
#define F_OUT  256
#define HEADS  8
#define MAXN   50048
#define MAXE   860000

// -------- scratch (__device__ globals; no allocation allowed) --------
__device__ __align__(16) __half g_hh[(size_t)MAXN * F_OUT];   // ~25.6 MB
__device__ __align__(16) float g_asrc[(size_t)MAXN * HEADS];
__device__ __align__(16) float g_adst[(size_t)MAXN * HEADS];
__device__ int g_deg[MAXN];
__device__ int g_rowstart[MAXN];
__device__ int g_cursor[MAXN];
__device__ int g_csr_src[MAXE];
__device__ int g_total;

// ============================================================================
// Kernel 1: tf32 tensor-core GEMM  h = x @ W  (fp16 output)
//   128x128 tile, BK=16, 2-stage cp.async, 8 warps (2x4), m16n8k8.
// ============================================================================
#define GBM 128
#define GBN 128
#define GBK 16
#define ASTR 20
#define BSTR 136
#define KTILES (F_IN / GBK)

__device__ __forceinline__ uint32_t f2tf32(float v) {
    uint32_t u;
    asm("cvt.rna.tf32.f32 %0, %1;" : "=r"(u) : "f"(v));
    return u;
}

__device__ __forceinline__ void cp16(uint32_t smem_addr, const void* gptr, int pred_bytes) {
    asm volatile("cp.async.cg.shared.global [%0], [%1], 16, %2;"
                 :: "r"(smem_addr), "l"(gptr), "r"(pred_bytes));
}

__global__ __launch_bounds__(256, 2) void gemm_tf32_kernel(
    const float* __restrict__ X, const float* __restrict__ W, int N)
{
    __shared__ float As[2][GBM * ASTR];
    __shared__ float Bs[2][GBK * BSTR];

    const int tid  = threadIdx.x;
    const int lane = tid & 31;
    const int warp = tid >> 5;
    const int wm = warp & 1;
    const int wn = warp >> 1;
    const int tg = lane & 3;
    const int gp = lane >> 2;

    const int brow = blockIdx.x * GBM;
    const int bcol = blockIdx.y * GBN;

    const int a_row0 = tid >> 2;
    const int a_quad = (tid & 3) << 2;
    const int b_k0  = tid >> 5;
    const int b_c4  = lane << 2;

    uint32_t as_base = (uint32_t)__cvta_generic_to_shared(&As[0][0]);
    uint32_t bs_base = (uint32_t)__cvta_generic_to_shared(&Bs[0][0]);

    float acc[4][4][4];
#pragma unroll
    for (int mt = 0; mt < 4; mt++)
#pragma unroll
        for (int nt = 0; nt < 4; nt++)
#pragma unroll
            for (int r = 0; r < 4; r++) acc[mt][nt][r] = 0.f;

    auto prefetch = [&](int s, int kt) {
#pragma unroll
        for (int i = 0; i < 2; i++) {
            int row = a_row0 + (i << 6);
            int grow = brow + row;
            int ok = (grow < N) ? 16 : 0;
            uint32_t dst = as_base + (uint32_t)((s * GBM * ASTR + row * ASTR + a_quad) << 2);
            cp16(dst, &X[(size_t)grow * F_IN + kt + a_quad], ok);
        }
#pragma unroll
        for (int i = 0; i < 2; i++) {
            int k = b_k0 + (i << 3);
            uint32_t dst = bs_base + (uint32_t)((s * GBK * BSTR + k * BSTR + b_c4) << 2);
            cp16(dst, &W[(size_t)(kt + k) * F_OUT + bcol + b_c4], 16);
        }
        asm volatile("cp.async.commit_group;");
    };

    prefetch(0, 0);

    for (int t = 0; t < KTILES; t++) {
        const int s = t & 1;
        if (t + 1 < KTILES) {
            prefetch(s ^ 1, (t + 1) * GBK);
            asm volatile("cp.async.wait_group 1;");
        } else {
            asm volatile("cp.async.wait_group 0;");
        }
        __syncthreads();

#pragma unroll
        for (int ks = 0; ks < 2; ks++) {
            const int k8 = ks << 3;
            uint32_t afr[4][4];
#pragma unroll
            for (int mt = 0; mt < 4; mt++) {
                int r0 = wm * 64 + mt * 16 + gp;
                const float* ap = &As[s][r0 * ASTR + k8 + tg];
                afr[mt][0] = f2tf32(ap[0]);
                afr[mt][1] = f2tf32(ap[8 * ASTR]);
                afr[mt][2] = f2tf32(ap[4]);
                afr[mt][3] = f2tf32(ap[8 * ASTR + 4]);
            }
            uint32_t bfr[4][2];
#pragma unroll
            for (int nt = 0; nt < 4; nt++) {
                int c0 = wn * 32 + nt * 8 + gp;
                const float* bp = &Bs[s][(k8 + tg) * BSTR + c0];
                bfr[nt][0] = f2tf32(bp[0]);
                bfr[nt][1] = f2tf32(bp[4 * BSTR]);
            }
#pragma unroll
            for (int mt = 0; mt < 4; mt++)
#pragma unroll
                for (int nt = 0; nt < 4; nt++) {
                    asm volatile(
                        "mma.sync.aligned.m16n8k8.row.col.f32.tf32.tf32.f32 "
                        "{%0,%1,%2,%3}, {%4,%5,%6,%7}, {%8,%9}, {%0,%1,%2,%3};"
                        : "+f"(acc[mt][nt][0]), "+f"(acc[mt][nt][1]),
                          "+f"(acc[mt][nt][2]), "+f"(acc[mt][nt][3])
                        : "r"(afr[mt][0]), "r"(afr[mt][1]),
                          "r"(afr[mt][2]), "r"(afr[mt][3]),
                          "r"(bfr[nt][0]), "r"(bfr[nt][1]));
                }
        }
        __syncthreads();
    }

    // ---- epilogue: fp16 store (adjacent channel pair per thread) ----
#pragma unroll
    for (int mt = 0; mt < 4; mt++) {
        int r0 = brow + wm * 64 + mt * 16 + gp;
        int r1 = r0 + 8;
#pragma unroll
        for (int nt = 0; nt < 4; nt++) {
            int c = bcol + wn * 32 + nt * 8 + tg * 2;
            if (r0 < N)
                *(__half2*)&g_hh[(size_t)r0 * F_OUT + c] =
                    __floats2half2_rn(acc[mt][nt][0], acc[mt][nt][1]);
            if (r1 < N)
                *(__half2*)&g_hh[(size_t)r1 * F_OUT + c] =
                    __floats2half2_rn(acc[mt][nt][2], acc[mt][nt][3]);
        }
    }
}

// ============================================================================
// Kernel 2: attention dots from fp16 h. 128 thr/node; warp w = heads 2w,2w+1.
//   Half-warp (16 lanes x half2 = 32 channels) reduces one head.
// ============================================================================
__global__ __launch_bounds__(128) void attdot_kernel(
    const float* __restrict__ att_src, const float* __restrict__ att_dst)
{
    const int n = blockIdx.x;
    const int tid = threadIdx.x;           // 0..127, half2 index in row
    const int lane = tid & 31;
    const int w = tid >> 5;
    const int h = (tid >> 4);              // head of this half-warp (0..7)

    float2 hv = __half22float2(*(const __half2*)&g_hh[(size_t)n * F_OUT + tid * 2]);
    float2 avs = *(const float2*)&att_src[tid * 2];
    float2 avd = *(const float2*)&att_dst[tid * 2];

    float s = hv.x * avs.x + hv.y * avs.y;
    float d = hv.x * avd.x + hv.y * avd.y;
#pragma unroll
    for (int o = 8; o > 0; o >>= 1) {
        s += __shfl_down_sync(0xffffffffu, s, o, 16);
        d += __shfl_down_sync(0xffffffffu, d, o, 16);
    }
    if ((lane & 15) == 0) {
        g_asrc[n * HEADS + h] = s;
        g_adst[n * HEADS + h] = d;
    }
    if (tid == 0) {
        g_deg[n] = 1;                      // self loop pre-counted
        if (n == 0) g_total = 0;
    }
    (void)w;
}

// ============================================================================
// Kernel 3: degree count over real edges
// ============================================================================
__global__ __launch_bounds__(256) void count_kernel(const int* __restrict__ ei, int E)
{
    int e = blockIdx.x * blockDim.x + threadIdx.x;
    if (e >= E) return;
    atomicAdd(&g_deg[ei[E + e]], 1);
}

// ============================================================================
// Kernel 4: segment allocation (order-free). Block scan + 1 atomic/block.
// ============================================================================
__global__ __launch_bounds__(256) void alloc_kernel(int N)
{
    __shared__ int warp_excl[8];
    __shared__ int blk_base;

    const int tid = threadIdx.x;
    const int lane = tid & 31;
    const int w = tid >> 5;
    const int n = blockIdx.x * 256 + tid;

    int deg = (n < N) ? g_deg[n] : 0;

    int incl = deg;
#pragma unroll
    for (int off = 1; off < 32; off <<= 1) {
        int v = __shfl_up_sync(0xffffffffu, incl, off);
        if (lane >= off) incl += v;
    }
    if (lane == 31) warp_excl[w] = incl;
    __syncthreads();
    if (tid == 0) {
        int run = 0;
#pragma unroll
        for (int i = 0; i < 8; i++) { int t = warp_excl[i]; warp_excl[i] = run; run += t; }
        blk_base = atomicAdd(&g_total, run);
    }
    __syncthreads();

    if (n < N) {
        int start = blk_base + warp_excl[w] + incl - deg;
        g_rowstart[n] = start;
        g_cursor[n]   = start;
    }
}

// ============================================================================
// Kernel 5: CSR fill (edges + self loops): src only.
// ============================================================================
__global__ __launch_bounds__(256) void fill_kernel(const int* __restrict__ ei, int E, int N)
{
    int e = blockIdx.x * blockDim.x + threadIdx.x;
    int total = E + N;
    if (e >= total) return;
    int src, dst;
    if (e < E) { src = ei[e]; dst = ei[E + e]; }
    else       { src = dst = e - E; }
    int pos = atomicAdd(&g_cursor[dst], 1);
    g_csr_src[pos] = src;
}

// ============================================================================
// Kernel 6: fused gather. 128 thr/node; thread owns half2 (2 channels).
//   Warp w covers heads 2w (lanes 0-15) and 2w+1 (lanes 16-31).
//   Exp weights computed lane-distributed (lanes 0-7), shfl-broadcast.
// ============================================================================
__global__ __launch_bounds__(128) void gather_kernel(
    float* __restrict__ out, const float* __restrict__ bias)
{
    const int n = blockIdx.x;
    const int tid = threadIdx.x;          // half2 index within row
    const int lane = tid & 31;
    const int w = tid >> 5;
    const int j = lane >> 4;              // head-in-warp (0/1)
    const int h = (w << 1) + j;           // my head

    const int beg = g_rowstart[n];
    const int end = beg + g_deg[n];

    const float adst_me = g_adst[n * HEADS + h];
    // weight-computation assignment for lanes 0..7: edge i = lane&3, head jj = lane>>2
    const int wi = lane & 3;
    const int wh = (w << 1) + ((lane >> 2) & 1);
    const float adst_w = g_adst[n * HEADS + wh];

    float accx = 0.f, accy = 0.f;
    float denom = 0.f;

    const __half2* __restrict__ H = (const __half2*)g_hh;

    int i = beg;
    for (; i + 3 < end; i += 4) {
        int s0 = __ldg(&g_csr_src[i]);
        int s1 = __ldg(&g_csr_src[i + 1]);
        int s2 = __ldg(&g_csr_src[i + 2]);
        int s3 = __ldg(&g_csr_src[i + 3]);

        float wv = 0.f;
        if (lane < 8) {
            int s_sel = (wi == 0) ? s0 : (wi == 1) ? s1 : (wi == 2) ? s2 : s3;
            float a = g_asrc[s_sel * HEADS + wh] + adst_w;
            a = a > 0.f ? a : 0.2f * a;
            wv = __expf(a);
        }
        int base = j << 2;
        float w0 = __shfl_sync(0xffffffffu, wv, base + 0);
        float w1 = __shfl_sync(0xffffffffu, wv, base + 1);
        float w2 = __shfl_sync(0xffffffffu, wv, base + 2);
        float w3 = __shfl_sync(0xffffffffu, wv, base + 3);

        float2 h0 = __half22float2(H[(size_t)s0 * 128 + tid]);
        float2 h1 = __half22float2(H[(size_t)s1 * 128 + tid]);
        float2 h2 = __half22float2(H[(size_t)s2 * 128 + tid]);
        float2 h3 = __half22float2(H[(size_t)s3 * 128 + tid]);

        accx = fmaf(w0, h0.x, accx); accy = fmaf(w0, h0.y, accy);
        accx = fmaf(w1, h1.x, accx); accy = fmaf(w1, h1.y, accy);
        accx = fmaf(w2, h2.x, accx); accy = fmaf(w2, h2.y, accy);
        accx = fmaf(w3, h3.x, accx); accy = fmaf(w3, h3.y, accy);
        denom += (w0 + w1) + (w2 + w3);
    }
    for (; i < end; i++) {
        int s0 = __ldg(&g_csr_src[i]);
        float wv = 0.f;
        if ((lane & 15) == 0) {           // lanes 0 and 16 compute their head's w
            float a = g_asrc[s0 * HEADS + h] + adst_me;
            a = a > 0.f ? a : 0.2f * a;
            wv = __expf(a);
        }
        float w0 = __shfl_sync(0xffffffffu, wv, j << 4);
        float2 h0 = __half22float2(H[(size_t)s0 * 128 + tid]);
        accx = fmaf(w0, h0.x, accx);
        accy = fmaf(w0, h0.y, accy);
        denom += w0;
    }

    float inv = 1.f / (denom + 1e-16f);
    float2 b = *(const float2*)&bias[tid * 2];
    float vx = accx * inv + b.x;
    float vy = accy * inv + b.y;
    vx = vx > 0.f ? vx : expm1f(vx);
    vy = vy > 0.f ? vy : expm1f(vy);
    *(float2*)&out[(size_t)n * F_OUT + tid * 2] = make_float2(vx, vy);
}

// ============================================================================
extern "C" void kernel_launch(void* const* d_in, const int* in_sizes, int n_in,
                              void* d_out, int out_size)
{
    const float* x       = (const float*)d_in[0];
    const int*   ei      = (const int*)  d_in[1];
    const float* W       = (const float*)d_in[2];
    const float* att_src = (const float*)d_in[3];
    const float* att_dst = (const float*)d_in[4];
    const float* bias    = (const float*)d_in[5];
    float* out = (float*)d_out;

    const int N = in_sizes[0] / F_IN;     // 50000
    const int E = in_sizes[1] / 2;        // 800000
    const int total = E + N;

    dim3 ggrid((N + GBM - 1) / GBM, F_OUT / GBN);
    gemm_tf32_kernel<<<ggrid, 256>>>(x, W, N);

    attdot_kernel<<<N, 128>>>(att_src, att_dst);

    count_kernel<<<(E + 255) / 256, 256>>>(ei, E);
    alloc_kernel<<<(N + 255) / 256, 256>>>(N);
    fill_kernel<<<(total + 255) / 256, 256>>>(ei, E, N);

    gather_kernel<<<N, 128>>>(out, bias);
}

// round 7
// speedup vs baseline: 2.6974x; 1.1090x over previous
#include <cuda_runtime.h>
#include <cuda_fp16.h>
#include <cuda_bf16.h>
#include <cstdint>

// GATLayer: tf32 cp.async GEMM (fp16 h + fused att dots in epilogue) ->
// CSR build (count/alloc/fill, fill also precomputes fp16 exp-weights) ->
// fused gather (weighted sum + normalize + bias + ELU).
//
// N = 50000, F_IN = 256, HEADS = 8, C = 32, E = 800000 (+N self loops).

#define F_IN   256
#define F_OUT  256
#define HEADS  8
#define MAXN   50048
#define MAXE   860000

// -------- scratch (__device__ globals; no allocation allowed) --------
__device__ __align__(16) __half g_hh[(size_t)MAXN * F_OUT];     // ~25.6 MB
__device__ __align__(16) float g_asrc[(size_t)MAXN * HEADS];
__device__ __align__(16) float g_adst[(size_t)MAXN * HEADS];
__device__ __align__(16) __half g_wcsr[(size_t)MAXE * HEADS];   // ~13.8 MB
__device__ int g_deg[MAXN];
__device__ int g_rowstart[MAXN];
__device__ int g_cursor[MAXN];
__device__ int g_csr_src[MAXE];
__device__ int g_total;

// ============================================================================
// Kernel 1: tf32 GEMM h = x@W, fp16 out, fused per-row per-head att dots.
//   128x128 tile, BK=16, 2-stage cp.async, 8 warps (2x4), m16n8k8.
// ============================================================================
#define GBM 128
#define GBN 128
#define GBK 16
#define ASTR 20
#define BSTR 136
#define KTILES (F_IN / GBK)

__device__ __forceinline__ uint32_t f2tf32(float v) {
    uint32_t u;
    asm("cvt.rna.tf32.f32 %0, %1;" : "=r"(u) : "f"(v));
    return u;
}

__device__ __forceinline__ void cp16(uint32_t smem_addr, const void* gptr, int pred_bytes) {
    asm volatile("cp.async.cg.shared.global [%0], [%1], 16, %2;"
                 :: "r"(smem_addr), "l"(gptr), "r"(pred_bytes));
}

__global__ __launch_bounds__(256, 2) void gemm_tf32_kernel(
    const float* __restrict__ X, const float* __restrict__ W,
    const float* __restrict__ att_src, const float* __restrict__ att_dst, int N)
{
    __shared__ float As[2][GBM * ASTR];
    __shared__ float Bs[2][GBK * BSTR];

    const int tid  = threadIdx.x;
    const int lane = tid & 31;
    const int warp = tid >> 5;
    const int wm = warp & 1;
    const int wn = warp >> 1;
    const int tg = lane & 3;
    const int gp = lane >> 2;

    const int brow = blockIdx.x * GBM;
    const int bcol = blockIdx.y * GBN;

    const int a_row0 = tid >> 2;
    const int a_quad = (tid & 3) << 2;
    const int b_k0  = tid >> 5;
    const int b_c4  = lane << 2;

    uint32_t as_base = (uint32_t)__cvta_generic_to_shared(&As[0][0]);
    uint32_t bs_base = (uint32_t)__cvta_generic_to_shared(&Bs[0][0]);

    float acc[4][4][4];
#pragma unroll
    for (int mt = 0; mt < 4; mt++)
#pragma unroll
        for (int nt = 0; nt < 4; nt++)
#pragma unroll
            for (int r = 0; r < 4; r++) acc[mt][nt][r] = 0.f;

    auto prefetch = [&](int s, int kt) {
#pragma unroll
        for (int i = 0; i < 2; i++) {
            int row = a_row0 + (i << 6);
            int grow = brow + row;
            int ok = (grow < N) ? 16 : 0;
            uint32_t dst = as_base + (uint32_t)((s * GBM * ASTR + row * ASTR + a_quad) << 2);
            cp16(dst, &X[(size_t)grow * F_IN + kt + a_quad], ok);
        }
#pragma unroll
        for (int i = 0; i < 2; i++) {
            int k = b_k0 + (i << 3);
            uint32_t dst = bs_base + (uint32_t)((s * GBK * BSTR + k * BSTR + b_c4) << 2);
            cp16(dst, &W[(size_t)(kt + k) * F_OUT + bcol + b_c4], 16);
        }
        asm volatile("cp.async.commit_group;");
    };

    prefetch(0, 0);

    for (int t = 0; t < KTILES; t++) {
        const int s = t & 1;
        if (t + 1 < KTILES) {
            prefetch(s ^ 1, (t + 1) * GBK);
            asm volatile("cp.async.wait_group 1;");
        } else {
            asm volatile("cp.async.wait_group 0;");
        }
        __syncthreads();

#pragma unroll
        for (int ks = 0; ks < 2; ks++) {
            const int k8 = ks << 3;
            uint32_t afr[4][4];
#pragma unroll
            for (int mt = 0; mt < 4; mt++) {
                int r0 = wm * 64 + mt * 16 + gp;
                const float* ap = &As[s][r0 * ASTR + k8 + tg];
                afr[mt][0] = f2tf32(ap[0]);
                afr[mt][1] = f2tf32(ap[8 * ASTR]);
                afr[mt][2] = f2tf32(ap[4]);
                afr[mt][3] = f2tf32(ap[8 * ASTR + 4]);
            }
            uint32_t bfr[4][2];
#pragma unroll
            for (int nt = 0; nt < 4; nt++) {
                int c0 = wn * 32 + nt * 8 + gp;
                const float* bp = &Bs[s][(k8 + tg) * BSTR + c0];
                bfr[nt][0] = f2tf32(bp[0]);
                bfr[nt][1] = f2tf32(bp[4 * BSTR]);
            }
#pragma unroll
            for (int mt = 0; mt < 4; mt++)
#pragma unroll
                for (int nt = 0; nt < 4; nt++) {
                    asm volatile(
                        "mma.sync.aligned.m16n8k8.row.col.f32.tf32.tf32.f32 "
                        "{%0,%1,%2,%3}, {%4,%5,%6,%7}, {%8,%9}, {%0,%1,%2,%3};"
                        : "+f"(acc[mt][nt][0]), "+f"(acc[mt][nt][1]),
                          "+f"(acc[mt][nt][2]), "+f"(acc[mt][nt][3])
                        : "r"(afr[mt][0]), "r"(afr[mt][1]),
                          "r"(afr[mt][2]), "r"(afr[mt][3]),
                          "r"(bfr[nt][0]), "r"(bfr[nt][1]));
                }
        }
        __syncthreads();
    }

    // ---- epilogue: fp16 h store + fused att dots ----
    const int head = (bcol >> 5) + wn;        // this warp's head
    float asv[8], adv[8];
#pragma unroll
    for (int nt = 0; nt < 4; nt++) {
        int c = bcol + wn * 32 + nt * 8 + tg * 2;
        asv[nt * 2]     = att_src[c];
        asv[nt * 2 + 1] = att_src[c + 1];
        adv[nt * 2]     = att_dst[c];
        adv[nt * 2 + 1] = att_dst[c + 1];
    }

#pragma unroll
    for (int mt = 0; mt < 4; mt++) {
        int r0 = brow + wm * 64 + mt * 16 + gp;
        int r1 = r0 + 8;
        float s0 = 0.f, d0 = 0.f, s1 = 0.f, d1 = 0.f;
#pragma unroll
        for (int nt = 0; nt < 4; nt++) {
            int c = bcol + wn * 32 + nt * 8 + tg * 2;
            if (r0 < N)
                *(__half2*)&g_hh[(size_t)r0 * F_OUT + c] =
                    __floats2half2_rn(acc[mt][nt][0], acc[mt][nt][1]);
            if (r1 < N)
                *(__half2*)&g_hh[(size_t)r1 * F_OUT + c] =
                    __floats2half2_rn(acc[mt][nt][2], acc[mt][nt][3]);
            s0 = fmaf(acc[mt][nt][0], asv[nt * 2], fmaf(acc[mt][nt][1], asv[nt * 2 + 1], s0));
            d0 = fmaf(acc[mt][nt][0], adv[nt * 2], fmaf(acc[mt][nt][1], adv[nt * 2 + 1], d0));
            s1 = fmaf(acc[mt][nt][2], asv[nt * 2], fmaf(acc[mt][nt][3], asv[nt * 2 + 1], s1));
            d1 = fmaf(acc[mt][nt][2], adv[nt * 2], fmaf(acc[mt][nt][3], adv[nt * 2 + 1], d1));
        }
        // reduce across the quad (lanes gp*4 + tg, tg = 0..3)
#pragma unroll
        for (int o = 1; o < 4; o <<= 1) {
            s0 += __shfl_xor_sync(0xffffffffu, s0, o);
            d0 += __shfl_xor_sync(0xffffffffu, d0, o);
            s1 += __shfl_xor_sync(0xffffffffu, s1, o);
            d1 += __shfl_xor_sync(0xffffffffu, d1, o);
        }
        if (tg == 0) {
            if (r0 < N) { g_asrc[r0 * HEADS + head] = s0; g_adst[r0 * HEADS + head] = d0; }
            if (r1 < N) { g_asrc[r1 * HEADS + head] = s1; g_adst[r1 * HEADS + head] = d1; }
            if (bcol == 0 && wn == 0) {      // seed self-loop degree once per row
                if (r0 < N) g_deg[r0] = 1;
                if (r1 < N) g_deg[r1] = 1;
            }
        }
    }
    if (blockIdx.x == 0 && blockIdx.y == 0 && tid == 0) g_total = 0;
}

// ============================================================================
// Kernel 2: degree count over real edges
// ============================================================================
__global__ __launch_bounds__(256) void count_kernel(const int* __restrict__ ei, int E)
{
    int e = blockIdx.x * blockDim.x + threadIdx.x;
    if (e >= E) return;
    atomicAdd(&g_deg[ei[E + e]], 1);
}

// ============================================================================
// Kernel 3: segment allocation (order-free). Block scan + 1 atomic/block.
// ============================================================================
__global__ __launch_bounds__(256) void alloc_kernel(int N)
{
    __shared__ int warp_excl[8];
    __shared__ int blk_base;

    const int tid = threadIdx.x;
    const int lane = tid & 31;
    const int w = tid >> 5;
    const int n = blockIdx.x * 256 + tid;

    int deg = (n < N) ? g_deg[n] : 0;

    int incl = deg;
#pragma unroll
    for (int off = 1; off < 32; off <<= 1) {
        int v = __shfl_up_sync(0xffffffffu, incl, off);
        if (lane >= off) incl += v;
    }
    if (lane == 31) warp_excl[w] = incl;
    __syncthreads();
    if (tid == 0) {
        int run = 0;
#pragma unroll
        for (int i = 0; i < 8; i++) { int t = warp_excl[i]; warp_excl[i] = run; run += t; }
        blk_base = atomicAdd(&g_total, run);
    }
    __syncthreads();

    if (n < N) {
        int start = blk_base + warp_excl[w] + incl - deg;
        g_rowstart[n] = start;
        g_cursor[n]   = start;
    }
}

// ============================================================================
// Kernel 4: CSR fill: src index + 8 fp16 exp-weights per edge (one STG.128).
// ============================================================================
__global__ __launch_bounds__(256) void fill_kernel(const int* __restrict__ ei, int E, int N)
{
    int e = blockIdx.x * blockDim.x + threadIdx.x;
    int total = E + N;
    if (e >= total) return;
    int src, dst;
    if (e < E) { src = ei[e]; dst = ei[E + e]; }
    else       { src = dst = e - E; }

    int pos = atomicAdd(&g_cursor[dst], 1);
    g_csr_src[pos] = src;

    float4 s0 = *(const float4*)&g_asrc[src * HEADS];
    float4 s1 = *(const float4*)&g_asrc[src * HEADS + 4];
    float4 d0 = *(const float4*)&g_adst[dst * HEADS];
    float4 d1 = *(const float4*)&g_adst[dst * HEADS + 4];

    float a[8] = {s0.x + d0.x, s0.y + d0.y, s0.z + d0.z, s0.w + d0.w,
                  s1.x + d1.x, s1.y + d1.y, s1.z + d1.z, s1.w + d1.w};
#pragma unroll
    for (int h = 0; h < 8; h++) {
        float v = a[h];
        v = v > 0.f ? v : 0.2f * v;
        a[h] = __expf(v);
    }
    __half2 p0 = __floats2half2_rn(a[0], a[1]);
    __half2 p1 = __floats2half2_rn(a[2], a[3]);
    __half2 p2 = __floats2half2_rn(a[4], a[5]);
    __half2 p3 = __floats2half2_rn(a[6], a[7]);
    uint4 pk;
    pk.x = *(uint32_t*)&p0; pk.y = *(uint32_t*)&p1;
    pk.z = *(uint32_t*)&p2; pk.w = *(uint32_t*)&p3;
    *(uint4*)&g_wcsr[(size_t)pos * HEADS] = pk;
}

// ============================================================================
// Kernel 5: fused gather. 128 thr/node; thread owns half2 (2 channels).
//   Warp w covers heads 2w (lanes 0-15) and 2w+1 (lanes 16-31).
// ============================================================================
__global__ __launch_bounds__(128) void gather_kernel(
    float* __restrict__ out, const float* __restrict__ bias)
{
    const int n = blockIdx.x;
    const int tid = threadIdx.x;
    const int lane = tid & 31;
    const int w = tid >> 5;
    const int j = lane >> 4;
    const int h = (w << 1) + j;           // my head

    const int beg = g_rowstart[n];
    const int end = beg + g_deg[n];

    float accx = 0.f, accy = 0.f;
    float denom = 0.f;

    const __half2* __restrict__ H = (const __half2*)g_hh;

    int i = beg;
    for (; i + 3 < end; i += 4) {
        int s0 = __ldg(&g_csr_src[i]);
        int s1 = __ldg(&g_csr_src[i + 1]);
        int s2 = __ldg(&g_csr_src[i + 2]);
        int s3 = __ldg(&g_csr_src[i + 3]);
        float w0 = __half2float(__ldg(&g_wcsr[(size_t)(i    ) * HEADS + h]));
        float w1 = __half2float(__ldg(&g_wcsr[(size_t)(i + 1) * HEADS + h]));
        float w2 = __half2float(__ldg(&g_wcsr[(size_t)(i + 2) * HEADS + h]));
        float w3 = __half2float(__ldg(&g_wcsr[(size_t)(i + 3) * HEADS + h]));

        float2 h0 = __half22float2(H[(size_t)s0 * 128 + tid]);
        float2 h1 = __half22float2(H[(size_t)s1 * 128 + tid]);
        float2 h2 = __half22float2(H[(size_t)s2 * 128 + tid]);
        float2 h3 = __half22float2(H[(size_t)s3 * 128 + tid]);

        accx = fmaf(w0, h0.x, accx); accy = fmaf(w0, h0.y, accy);
        accx = fmaf(w1, h1.x, accx); accy = fmaf(w1, h1.y, accy);
        accx = fmaf(w2, h2.x, accx); accy = fmaf(w2, h2.y, accy);
        accx = fmaf(w3, h3.x, accx); accy = fmaf(w3, h3.y, accy);
        denom += (w0 + w1) + (w2 + w3);
    }
    for (; i < end; i++) {
        int s0 = __ldg(&g_csr_src[i]);
        float w0 = __half2float(__ldg(&g_wcsr[(size_t)i * HEADS + h]));
        float2 h0 = __half22float2(H[(size_t)s0 * 128 + tid]);
        accx = fmaf(w0, h0.x, accx);
        accy = fmaf(w0, h0.y, accy);
        denom += w0;
    }

    float inv = 1.f / (denom + 1e-16f);
    float2 b = *(const float2*)&bias[tid * 2];
    float vx = accx * inv + b.x;
    float vy = accy * inv + b.y;
    vx = vx > 0.f ? vx : expm1f(vx);
    vy = vy > 0.f ? vy : expm1f(vy);
    *(float2*)&out[(size_t)n * F_OUT + tid * 2] = make_float2(vx, vy);
}

// ============================================================================
extern "C" void kernel_launch(void* const* d_in, const int* in_sizes, int n_in,
                              void* d_out, int out_size)
{
    const float* x       = (const float*)d_in[0];
    const int*   ei      = (const int*)  d_in[1];
    const float* W       = (const float*)d_in[2];
    const float* att_src = (const float*)d_in[3];
    const float* att_dst = (const float*)d_in[4];
    const float* bias    = (const float*)d_in[5];
    float* out = (float*)d_out;

    const int N = in_sizes[0] / F_IN;     // 50000
    const int E = in_sizes[1] / 2;        // 800000
    const int total = E + N;

    dim3 ggrid((N + GBM - 1) / GBM, F_OUT / GBN);
    gemm_tf32_kernel<<<ggrid, 256>>>(x, W, att_src, att_dst, N);

    count_kernel<<<(E + 255) / 256, 256>>>(ei, E);
    alloc_kernel<<<(N + 255) / 256, 256>>>(N);
    fill_kernel<<<(total + 255) / 256, 256>>>(ei, E, N);

    gather_kernel<<<N, 128>>>(out, bias);
}

// round 8
// speedup vs baseline: 3.4792x; 1.2898x over previous
#include <cuda_runtime.h>
#include <cuda_fp16.h>
#include <cuda_bf16.h>
#include <cstdint>

// GATLayer: tf32 cp.async GEMM (fp16 h + fused att dots + overlapped edge
// counting via specialized blocks) -> alloc (self-restoring deg reset) ->
// fill (csr_src + fp16 exp-weights) -> gather (64 thr/node, uint2 loads).
//
// N = 50000, F_IN = 256, HEADS = 8, C = 32, E = 800000 (+N self loops).

#define F_IN   256
#define F_OUT  256
#define HEADS  8
#define MAXN   50048
#define MAXE   860000

// -------- scratch (__device__ globals; no allocation allowed) --------
// g_deg is zero at every kernel_launch invocation: static zero-init on the
// first call, and alloc_kernel re-zeroes each entry after reading it.
__device__ __align__(16) __half g_hh[(size_t)MAXN * F_OUT];     // ~25.6 MB
__device__ __align__(16) float g_asrc[(size_t)MAXN * HEADS];
__device__ __align__(16) float g_adst[(size_t)MAXN * HEADS];
__device__ __align__(16) __half g_wcsr[(size_t)MAXE * HEADS];   // ~13.8 MB
__device__ int g_deg[MAXN];        // edge counts only (self loop added in alloc)
__device__ int g_degout[MAXN];     // final degree incl. self loop
__device__ int g_rowstart[MAXN];
__device__ int g_cursor[MAXN];
__device__ int g_csr_src[MAXE];
__device__ int g_total;

// ============================================================================
// Kernel 1: tf32 GEMM h = x@W (fp16 out) + fused att dots.
//   grid (tiles_m, 3): y<2 -> GEMM column halves; y==2 -> edge counting.
// ============================================================================
#define GBM 128
#define GBN 128
#define GBK 16
#define ASTR 20
#define BSTR 136
#define KTILES (F_IN / GBK)

__device__ __forceinline__ uint32_t f2tf32(float v) {
    uint32_t u;
    asm("cvt.rna.tf32.f32 %0, %1;" : "=r"(u) : "f"(v));
    return u;
}

__device__ __forceinline__ void cp16(uint32_t smem_addr, const void* gptr, int pred_bytes) {
    asm volatile("cp.async.cg.shared.global [%0], [%1], 16, %2;"
                 :: "r"(smem_addr), "l"(gptr), "r"(pred_bytes));
}

__global__ __launch_bounds__(256, 2) void gemm_tf32_kernel(
    const float* __restrict__ X, const float* __restrict__ W,
    const float* __restrict__ att_src, const float* __restrict__ att_dst,
    const int* __restrict__ ei, int E, int N)
{
    const int tid  = threadIdx.x;

    // ---- specialized blocks: edge degree counting (overlaps with GEMM) ----
    if (blockIdx.y == 2) {
        const int stride = gridDim.x * 256;
        for (int e = blockIdx.x * 256 + tid; e < E; e += stride)
            atomicAdd(&g_deg[ei[E + e]], 1);
        if (blockIdx.x == 0 && tid == 0) g_total = 0;
        return;
    }

    __shared__ float As[2][GBM * ASTR];
    __shared__ float Bs[2][GBK * BSTR];

    const int lane = tid & 31;
    const int warp = tid >> 5;
    const int wm = warp & 1;
    const int wn = warp >> 1;
    const int tg = lane & 3;
    const int gp = lane >> 2;

    const int brow = blockIdx.x * GBM;
    const int bcol = blockIdx.y * GBN;

    const int a_row0 = tid >> 2;
    const int a_quad = (tid & 3) << 2;
    const int b_k0  = tid >> 5;
    const int b_c4  = lane << 2;

    uint32_t as_base = (uint32_t)__cvta_generic_to_shared(&As[0][0]);
    uint32_t bs_base = (uint32_t)__cvta_generic_to_shared(&Bs[0][0]);

    float acc[4][4][4];
#pragma unroll
    for (int mt = 0; mt < 4; mt++)
#pragma unroll
        for (int nt = 0; nt < 4; nt++)
#pragma unroll
            for (int r = 0; r < 4; r++) acc[mt][nt][r] = 0.f;

    auto prefetch = [&](int s, int kt) {
#pragma unroll
        for (int i = 0; i < 2; i++) {
            int row = a_row0 + (i << 6);
            int grow = brow + row;
            int ok = (grow < N) ? 16 : 0;
            uint32_t dst = as_base + (uint32_t)((s * GBM * ASTR + row * ASTR + a_quad) << 2);
            cp16(dst, &X[(size_t)grow * F_IN + kt + a_quad], ok);
        }
#pragma unroll
        for (int i = 0; i < 2; i++) {
            int k = b_k0 + (i << 3);
            uint32_t dst = bs_base + (uint32_t)((s * GBK * BSTR + k * BSTR + b_c4) << 2);
            cp16(dst, &W[(size_t)(kt + k) * F_OUT + bcol + b_c4], 16);
        }
        asm volatile("cp.async.commit_group;");
    };

    prefetch(0, 0);

    for (int t = 0; t < KTILES; t++) {
        const int s = t & 1;
        if (t + 1 < KTILES) {
            prefetch(s ^ 1, (t + 1) * GBK);
            asm volatile("cp.async.wait_group 1;");
        } else {
            asm volatile("cp.async.wait_group 0;");
        }
        __syncthreads();

#pragma unroll
        for (int ks = 0; ks < 2; ks++) {
            const int k8 = ks << 3;
            uint32_t afr[4][4];
#pragma unroll
            for (int mt = 0; mt < 4; mt++) {
                int r0 = wm * 64 + mt * 16 + gp;
                const float* ap = &As[s][r0 * ASTR + k8 + tg];
                afr[mt][0] = f2tf32(ap[0]);
                afr[mt][1] = f2tf32(ap[8 * ASTR]);
                afr[mt][2] = f2tf32(ap[4]);
                afr[mt][3] = f2tf32(ap[8 * ASTR + 4]);
            }
            uint32_t bfr[4][2];
#pragma unroll
            for (int nt = 0; nt < 4; nt++) {
                int c0 = wn * 32 + nt * 8 + gp;
                const float* bp = &Bs[s][(k8 + tg) * BSTR + c0];
                bfr[nt][0] = f2tf32(bp[0]);
                bfr[nt][1] = f2tf32(bp[4 * BSTR]);
            }
#pragma unroll
            for (int mt = 0; mt < 4; mt++)
#pragma unroll
                for (int nt = 0; nt < 4; nt++) {
                    asm volatile(
                        "mma.sync.aligned.m16n8k8.row.col.f32.tf32.tf32.f32 "
                        "{%0,%1,%2,%3}, {%4,%5,%6,%7}, {%8,%9}, {%0,%1,%2,%3};"
                        : "+f"(acc[mt][nt][0]), "+f"(acc[mt][nt][1]),
                          "+f"(acc[mt][nt][2]), "+f"(acc[mt][nt][3])
                        : "r"(afr[mt][0]), "r"(afr[mt][1]),
                          "r"(afr[mt][2]), "r"(afr[mt][3]),
                          "r"(bfr[nt][0]), "r"(bfr[nt][1]));
                }
        }
        __syncthreads();
    }

    // ---- epilogue: fp16 h store + fused att dots ----
    const int head = (bcol >> 5) + wn;        // this warp's head
    float asv[8], adv[8];
#pragma unroll
    for (int nt = 0; nt < 4; nt++) {
        int c = bcol + wn * 32 + nt * 8 + tg * 2;
        asv[nt * 2]     = att_src[c];
        asv[nt * 2 + 1] = att_src[c + 1];
        adv[nt * 2]     = att_dst[c];
        adv[nt * 2 + 1] = att_dst[c + 1];
    }

#pragma unroll
    for (int mt = 0; mt < 4; mt++) {
        int r0 = brow + wm * 64 + mt * 16 + gp;
        int r1 = r0 + 8;
        float s0 = 0.f, d0 = 0.f, s1 = 0.f, d1 = 0.f;
#pragma unroll
        for (int nt = 0; nt < 4; nt++) {
            int c = bcol + wn * 32 + nt * 8 + tg * 2;
            if (r0 < N)
                *(__half2*)&g_hh[(size_t)r0 * F_OUT + c] =
                    __floats2half2_rn(acc[mt][nt][0], acc[mt][nt][1]);
            if (r1 < N)
                *(__half2*)&g_hh[(size_t)r1 * F_OUT + c] =
                    __floats2half2_rn(acc[mt][nt][2], acc[mt][nt][3]);
            s0 = fmaf(acc[mt][nt][0], asv[nt * 2], fmaf(acc[mt][nt][1], asv[nt * 2 + 1], s0));
            d0 = fmaf(acc[mt][nt][0], adv[nt * 2], fmaf(acc[mt][nt][1], adv[nt * 2 + 1], d0));
            s1 = fmaf(acc[mt][nt][2], asv[nt * 2], fmaf(acc[mt][nt][3], asv[nt * 2 + 1], s1));
            d1 = fmaf(acc[mt][nt][2], adv[nt * 2], fmaf(acc[mt][nt][3], adv[nt * 2 + 1], d1));
        }
#pragma unroll
        for (int o = 1; o < 4; o <<= 1) {
            s0 += __shfl_xor_sync(0xffffffffu, s0, o);
            d0 += __shfl_xor_sync(0xffffffffu, d0, o);
            s1 += __shfl_xor_sync(0xffffffffu, s1, o);
            d1 += __shfl_xor_sync(0xffffffffu, d1, o);
        }
        if (tg == 0) {
            if (r0 < N) { g_asrc[r0 * HEADS + head] = s0; g_adst[r0 * HEADS + head] = d0; }
            if (r1 < N) { g_asrc[r1 * HEADS + head] = s1; g_adst[r1 * HEADS + head] = d1; }
        }
    }
}

// ============================================================================
// Kernel 2: segment allocation. deg = edge count + 1 (self loop).
//   Re-zeroes g_deg after reading (restores the zero invariant).
// ============================================================================
__global__ __launch_bounds__(256) void alloc_kernel(int N)
{
    __shared__ int warp_excl[8];
    __shared__ int blk_base;

    const int tid = threadIdx.x;
    const int lane = tid & 31;
    const int w = tid >> 5;
    const int n = blockIdx.x * 256 + tid;

    int deg = 0;
    if (n < N) {
        deg = g_deg[n] + 1;        // + self loop
        g_deg[n] = 0;              // restore zero for next launch
    }

    int incl = deg;
#pragma unroll
    for (int off = 1; off < 32; off <<= 1) {
        int v = __shfl_up_sync(0xffffffffu, incl, off);
        if (lane >= off) incl += v;
    }
    if (lane == 31) warp_excl[w] = incl;
    __syncthreads();
    if (tid == 0) {
        int run = 0;
#pragma unroll
        for (int i = 0; i < 8; i++) { int t = warp_excl[i]; warp_excl[i] = run; run += t; }
        blk_base = atomicAdd(&g_total, run);
    }
    __syncthreads();

    if (n < N) {
        int start = blk_base + warp_excl[w] + incl - deg;
        g_rowstart[n] = start;
        g_cursor[n]   = start;
        g_degout[n]   = deg;
    }
}

// ============================================================================
// Kernel 3: CSR fill: src index + 8 fp16 exp-weights per edge (one STG.128).
// ============================================================================
__global__ __launch_bounds__(256) void fill_kernel(const int* __restrict__ ei, int E, int N)
{
    int e = blockIdx.x * blockDim.x + threadIdx.x;
    int total = E + N;
    if (e >= total) return;
    int src, dst;
    if (e < E) { src = ei[e]; dst = ei[E + e]; }
    else       { src = dst = e - E; }

    int pos = atomicAdd(&g_cursor[dst], 1);
    g_csr_src[pos] = src;

    float4 s0 = *(const float4*)&g_asrc[src * HEADS];
    float4 s1 = *(const float4*)&g_asrc[src * HEADS + 4];
    float4 d0 = *(const float4*)&g_adst[dst * HEADS];
    float4 d1 = *(const float4*)&g_adst[dst * HEADS + 4];

    float a[8] = {s0.x + d0.x, s0.y + d0.y, s0.z + d0.z, s0.w + d0.w,
                  s1.x + d1.x, s1.y + d1.y, s1.z + d1.z, s1.w + d1.w};
#pragma unroll
    for (int h = 0; h < 8; h++) {
        float v = a[h];
        v = v > 0.f ? v : 0.2f * v;
        a[h] = __expf(v);
    }
    __half2 p0 = __floats2half2_rn(a[0], a[1]);
    __half2 p1 = __floats2half2_rn(a[2], a[3]);
    __half2 p2 = __floats2half2_rn(a[4], a[5]);
    __half2 p3 = __floats2half2_rn(a[6], a[7]);
    uint4 pk;
    pk.x = *(uint32_t*)&p0; pk.y = *(uint32_t*)&p1;
    pk.z = *(uint32_t*)&p2; pk.w = *(uint32_t*)&p3;
    *(uint4*)&g_wcsr[(size_t)pos * HEADS] = pk;
}

// ============================================================================
// Kernel 4: fused gather. 64 threads per node (4 nodes / 256-block).
//   Thread t owns channels 4t..4t+3 (uint2 = 4 halves); head = t>>3.
//   Weight: direct per-lane LDG.16 (whole warp hits one 16B row: 1 sector).
// ============================================================================
__global__ __launch_bounds__(256) void gather_kernel(
    float* __restrict__ out, const float* __restrict__ bias, int N)
{
    const int node = blockIdx.x * 4 + (threadIdx.x >> 6);
    if (node >= N) return;
    const int t = threadIdx.x & 63;       // 0..63
    const int h = t >> 3;                 // head 0..7

    const int beg = g_rowstart[node];
    const int end = beg + g_degout[node];

    float a0 = 0.f, a1 = 0.f, a2 = 0.f, a3 = 0.f;
    float denom = 0.f;

    const uint2* __restrict__ H = (const uint2*)g_hh;   // row = 64 uint2

    int i = beg;
    for (; i + 3 < end; i += 4) {
        int s0 = __ldg(&g_csr_src[i]);
        int s1 = __ldg(&g_csr_src[i + 1]);
        int s2 = __ldg(&g_csr_src[i + 2]);
        int s3 = __ldg(&g_csr_src[i + 3]);
        float w0 = __half2float(__ldg(&g_wcsr[(size_t)(i    ) * HEADS + h]));
        float w1 = __half2float(__ldg(&g_wcsr[(size_t)(i + 1) * HEADS + h]));
        float w2 = __half2float(__ldg(&g_wcsr[(size_t)(i + 2) * HEADS + h]));
        float w3 = __half2float(__ldg(&g_wcsr[(size_t)(i + 3) * HEADS + h]));

        uint2 r0 = H[(size_t)s0 * 64 + t];
        uint2 r1 = H[(size_t)s1 * 64 + t];
        uint2 r2 = H[(size_t)s2 * 64 + t];
        uint2 r3 = H[(size_t)s3 * 64 + t];

        float2 lo, hi;
        lo = __half22float2(*(__half2*)&r0.x); hi = __half22float2(*(__half2*)&r0.y);
        a0 = fmaf(w0, lo.x, a0); a1 = fmaf(w0, lo.y, a1);
        a2 = fmaf(w0, hi.x, a2); a3 = fmaf(w0, hi.y, a3);
        lo = __half22float2(*(__half2*)&r1.x); hi = __half22float2(*(__half2*)&r1.y);
        a0 = fmaf(w1, lo.x, a0); a1 = fmaf(w1, lo.y, a1);
        a2 = fmaf(w1, hi.x, a2); a3 = fmaf(w1, hi.y, a3);
        lo = __half22float2(*(__half2*)&r2.x); hi = __half22float2(*(__half2*)&r2.y);
        a0 = fmaf(w2, lo.x, a0); a1 = fmaf(w2, lo.y, a1);
        a2 = fmaf(w2, hi.x, a2); a3 = fmaf(w2, hi.y, a3);
        lo = __half22float2(*(__half2*)&r3.x); hi = __half22float2(*(__half2*)&r3.y);
        a0 = fmaf(w3, lo.x, a0); a1 = fmaf(w3, lo.y, a1);
        a2 = fmaf(w3, hi.x, a2); a3 = fmaf(w3, hi.y, a3);

        denom += (w0 + w1) + (w2 + w3);
    }
    for (; i < end; i++) {
        int s0 = __ldg(&g_csr_src[i]);
        float w0 = __half2float(__ldg(&g_wcsr[(size_t)i * HEADS + h]));
        uint2 r0 = H[(size_t)s0 * 64 + t];
        float2 lo = __half22float2(*(__half2*)&r0.x);
        float2 hi = __half22float2(*(__half2*)&r0.y);
        a0 = fmaf(w0, lo.x, a0); a1 = fmaf(w0, lo.y, a1);
        a2 = fmaf(w0, hi.x, a2); a3 = fmaf(w0, hi.y, a3);
        denom += w0;
    }

    float inv = 1.f / (denom + 1e-16f);
    float4 b = *(const float4*)&bias[t * 4];
    float v0 = a0 * inv + b.x;
    float v1 = a1 * inv + b.y;
    float v2 = a2 * inv + b.z;
    float v3 = a3 * inv + b.w;
    v0 = v0 > 0.f ? v0 : expm1f(v0);
    v1 = v1 > 0.f ? v1 : expm1f(v1);
    v2 = v2 > 0.f ? v2 : expm1f(v2);
    v3 = v3 > 0.f ? v3 : expm1f(v3);
    *(float4*)&out[(size_t)node * F_OUT + t * 4] = make_float4(v0, v1, v2, v3);
}

// ============================================================================
extern "C" void kernel_launch(void* const* d_in, const int* in_sizes, int n_in,
                              void* d_out, int out_size)
{
    const float* x       = (const float*)d_in[0];
    const int*   ei      = (const int*)  d_in[1];
    const float* W       = (const float*)d_in[2];
    const float* att_src = (const float*)d_in[3];
    const float* att_dst = (const float*)d_in[4];
    const float* bias    = (const float*)d_in[5];
    float* out = (float*)d_out;

    const int N = in_sizes[0] / F_IN;     // 50000
    const int E = in_sizes[1] / 2;        // 800000
    const int total = E + N;

    dim3 ggrid((N + GBM - 1) / GBM, 3);   // y<2: GEMM, y==2: edge count
    gemm_tf32_kernel<<<ggrid, 256>>>(x, W, att_src, att_dst, ei, E, N);

    alloc_kernel<<<(N + 255) / 256, 256>>>(N);
    fill_kernel<<<(total + 255) / 256, 256>>>(ei, E, N);

    gather_kernel<<<(N + 3) / 4, 256>>>(out, bias, N);
}